// round 12
// baseline (speedup 1.0000x reference)
#include <cuda_runtime.h>
#include <cuda_bf16.h>
#include <math.h>
#include <stdint.h>

// ---------------- problem constants ----------------
#define CC      128
#define NHEAD   4
#define HEADD   32
#define NTOK    392
#define NPAD    400
#define NWIN    128
#define MROWS   50176
#define HIDD    512
#define SCALE_Q 0.17677669529663687f
#define LOG2E   1.4426950408889634f
#define QSCALE  (0.25503489337494845f)   // SCALE_Q * LOG2E
#define SMEM_ATT  64000     // attention: Ks + Vs, 400 rows x 80B
#define SMEM_G2   65536     // gemm: 2 stages x (A 16KB + B 16KB)

typedef __nv_bfloat16 bf16;

// ---------------- scratch (device globals) ----------------
__device__ __align__(16) bf16  g_win[MROWS * CC];
__device__ __align__(16) bf16  g_qkv[3 * MROWS * CC];   // bf16 (sel,w,head,n,d)
__device__ __align__(16) bf16  g_y[MROWS * CC];
__device__ __align__(16) float g_x1[MROWS * CC];
__device__ __align__(16) bf16  g_m1[MROWS * CC];
__device__ __align__(16) bf16  g_hid[MROWS * HIDD];
__device__ __align__(16) bf16  g_wb[196608];
__device__ __align__(16) float4 g_btabF[32 * 625 * 2 * 32]; // fp32 accumulator-frag bias*log2e

// ---------------- asm helpers ----------------
__device__ __forceinline__ void cp16(uint32_t dst, const void* src) {
    asm volatile("cp.async.cg.shared.global [%0], [%1], 16;\n" :: "r"(dst), "l"(src));
}
__device__ __forceinline__ uint32_t swz(int row, int kb) {        // SW128 (gemm)
    return (uint32_t)((row << 7) + (kb ^ ((row & 7) << 4)));
}
__device__ __forceinline__ float ex2f(float x) {
    float y;
    asm("ex2.approx.ftz.f32 %0, %1;" : "=f"(y) : "f"(x));
    return y;
}
#define LDSM4(R, addr) \
    asm volatile("ldmatrix.sync.aligned.m8n8.x4.shared.b16 {%0,%1,%2,%3}, [%4];\n" \
        : "=r"((R)[0]), "=r"((R)[1]), "=r"((R)[2]), "=r"((R)[3]) : "r"(addr))
#define LDSM4T(R, addr) \
    asm volatile("ldmatrix.sync.aligned.m8n8.x4.trans.shared.b16 {%0,%1,%2,%3}, [%4];\n" \
        : "=r"((R)[0]), "=r"((R)[1]), "=r"((R)[2]), "=r"((R)[3]) : "r"(addr))
#define MMA16816(d, a0,a1,a2,a3, b0,b1) \
    asm volatile("mma.sync.aligned.m16n8k16.row.col.f32.bf16.bf16.f32 " \
        "{%0,%1,%2,%3}, {%4,%5,%6,%7}, {%8,%9}, {%0,%1,%2,%3};\n" \
        : "+f"((d)[0]), "+f"((d)[1]), "+f"((d)[2]), "+f"((d)[3]) \
        : "r"(a0), "r"(a1), "r"(a2), "r"(a3), "r"(b0), "r"(b1))

__device__ __forceinline__ uint32_t packbf(float a, float b) {
    __nv_bfloat162 p = __floats2bfloat162_rn(a, b);
    return *(uint32_t*)&p;
}

// ---------------- prep: weights fp32->bf16 AND fp32 fragment bias table ----------------
__global__ void __launch_bounds__(256) prep_kernel(
        const float* __restrict__ s0, const float* __restrict__ s1,
        const float* __restrict__ s2, const float* __restrict__ s3,
        bf16* __restrict__ wb,
        const float* __restrict__ relt, float4* __restrict__ btabF) {
    int b = blockIdx.x;
    if (b < 192) {                          // weight conversion: 49152 float4
        int i = b * 256 + threadIdx.x;
        const float* s; int off;
        if (i < 12288)      { s = s0; off = 0; }
        else if (i < 16384) { s = s1; off = 12288; }
        else if (i < 32768) { s = s2; off = 16384; }
        else                { s = s3; off = 32768; }
        float4 v = ((const float4*)s)[i - off];
        ((uint2*)wb)[i] = make_uint2(packbf(v.x, v.y), packbf(v.z, v.w));
        return;
    }
    // bias table (pre-scaled by LOG2E), fp32 accumulator-fragment layout:
    // [tile t][half {A,B}][lane] -> float4
    int gid = (b - 192) * 256 + threadIdx.x;        // 0 .. 640000-1
    int lane = gid & 31;
    int t    = gid >> 5;                            // 0..19999
    int tile = t % 625;
    int hw_  = t / 625;
    int head = hw_ & 3, wt = hw_ >> 2;
    int mt = tile / 25, np = tile % 25;
    int r = lane >> 2, cb = (lane & 3) * 2;
    float vv[2][4];
    #pragma unroll
    for (int ri = 0; ri < 2; ++ri) {
        int row = mt * 16 + r + ri * 8;
        bool rowpad = row >= NTOK;
        int tn = 0, hn = 0, wn_ = 0, regn = 0;
        if (!rowpad) {
            tn = row / 49; hn = (row / 7) % 7; wn_ = row % 7;
            regn = ((wt & 4) ? (tn  < 4 ? 1 : 2) : 0) * 9
                 + ((wt & 2) ? (hn  < 4 ? 1 : 2) : 0) * 3
                 + ((wt & 1) ? (wn_ < 4 ? 1 : 2) : 0);
        }
        #pragma unroll
        for (int ci = 0; ci < 4; ++ci) {
            int col = np * 16 + cb + (ci & 1) + (ci >> 1) * 8;
            float v;
            if (col >= NTOK)      v = -100.f * LOG2E;
            else if (rowpad)      v = 0.f;
            else {
                int tm = col / 49, hm = (col / 7) % 7, wm_ = col % 7;
                int regm = ((wt & 4) ? (tm  < 4 ? 1 : 2) : 0) * 9
                         + ((wt & 2) ? (hm  < 4 ? 1 : 2) : 0) * 3
                         + ((wt & 1) ? (wm_ < 4 ? 1 : 2) : 0);
                int idx = (tn - tm + 7) * 169 + (hn - hm + 6) * 13 + (wn_ - wm_ + 6);
                float bb = relt[idx * NHEAD + head];
                v = ((regn == regm) ? bb : bb - 100.f) * LOG2E;
            }
            vv[ri][ci] = v;
        }
    }
    btabF[((size_t)t * 2 + 0) * 32 + lane] = make_float4(vv[0][0], vv[0][1], vv[1][0], vv[1][1]);
    btabF[((size_t)t * 2 + 1) * 32 + lane] = make_float4(vv[0][2], vv[0][3], vv[1][2], vv[1][3]);
}

// ---------------- LN1 (+shift/window-partition), bf16 out ----------------
__global__ void __launch_bounds__(256) ln_kernel(const float* __restrict__ x,
                                                 const float* __restrict__ gw,
                                                 const float* __restrict__ gb,
                                                 bf16* __restrict__ out) {
    int row  = blockIdx.x * 8 + (threadIdx.x >> 5);
    int lane = threadIdx.x & 31;
    int w = row / NTOK, n = row % NTOK;
    int dblk = w >> 6, hblk = (w >> 3) & 7, wblk = w & 7;
    int t = n / 49, hh = (n / 7) % 7, ww = n % 7;
    int gd = (dblk * 8 + t + 4) & 15;
    int gh = hblk * 7 + hh + 3; if (gh >= 56) gh -= 56;
    int gx = wblk * 7 + ww + 3; if (gx >= 56) gx -= 56;
    int src = (gd * 56 + gh) * 56 + gx;
    float4 v = *(const float4*)(x + (size_t)src * CC + lane * 4);
    float s  = v.x + v.y + v.z + v.w;
    float ss = v.x*v.x + v.y*v.y + v.z*v.z + v.w*v.w;
    #pragma unroll
    for (int o = 16; o; o >>= 1) {
        s  += __shfl_xor_sync(~0u, s,  o);
        ss += __shfl_xor_sync(~0u, ss, o);
    }
    float mu  = s * (1.f / CC);
    float var = ss * (1.f / CC) - mu * mu;
    float rs  = rsqrtf(var + 1e-5f);
    float4 gwv = *(const float4*)(gw + lane * 4);
    float4 gbv = *(const float4*)(gb + lane * 4);
    *(uint2*)(out + (size_t)row * CC + lane * 4) = make_uint2(
        packbf((v.x - mu) * rs * gwv.x + gbv.x, (v.y - mu) * rs * gwv.y + gbv.y),
        packbf((v.z - mu) * rs * gwv.z + gbv.z, (v.w - mu) * rs * gwv.w + gbv.w));
}

// ---------------- bf16 HMMA GEMM: 128x128 CTA, 4 warps @ 64x64 ----------------
// Single-buffered fragments (-32 regs) so TWO CTAs fit per SM (2 warps/SMSP).
// EPI: 0=QKV scatter  1=proj+reverse+residual+LN2(fused)  2=FC1+GELU  3=FC2+residual
template<int EPI, int ND, int KK>
__global__ void __launch_bounds__(128, 2) mgemm2(const bf16* __restrict__ A,
                                                 const bf16* __restrict__ B,
                                                 const float* __restrict__ bias,
                                                 const float* __restrict__ extra,
                                                 const float* __restrict__ lnw,
                                                 const float* __restrict__ lnb,
                                                 void* __restrict__ out2,
                                                 void* __restrict__ outv) {
    extern __shared__ char smc[];
    const uint32_t smb = (uint32_t)__cvta_generic_to_shared(smc);
    const int tid = threadIdx.x, lane = tid & 31, warp = tid >> 5;
    const int wm = warp >> 1, wn = warp & 1;          // 2x2 warp grid, 64x64 tiles
    const int m0 = blockIdx.x * 128, n0 = blockIdx.y * 128;
    constexpr int NCHUNK = KK / 64;

    float c[4][8][4];
    #pragma unroll
    for (int a = 0; a < 4; ++a)
        #pragma unroll
        for (int b = 0; b < 8; ++b)
            #pragma unroll
            for (int e = 0; e < 4; ++e) c[a][b][e] = 0.f;

    auto load = [&](int ch, int st) {
        uint32_t ab = smb + st * 32768, bb = ab + 16384;
        const char* Ap = (const char*)(A + (size_t)m0 * KK + ch * 64);
        const char* Bp = (const char*)(B + (size_t)n0 * KK + ch * 64);
        #pragma unroll
        for (int i = 0; i < 8; ++i) {
            int cid = tid + i * 128;
            int row = cid >> 3, kb = (cid & 7) * 16;
            cp16(ab + swz(row, kb), Ap + (size_t)row * (KK * 2) + kb);
            cp16(bb + swz(row, kb), Bp + (size_t)row * (KK * 2) + kb);
        }
        asm volatile("cp.async.commit_group;\n");
    };

    load(0, 0);
    if (NCHUNK > 1) load(1, 1);
    asm volatile("cp.async.wait_group %0;\n" :: "n"(1));
    if (NCHUNK == 1) asm volatile("cp.async.wait_group 0;\n");
    __syncthreads();

    #pragma unroll 1
    for (int ch = 0; ch < NCHUNK; ++ch) {
        const int st = ch & 1;
        const uint32_t ab = smb + st * 32768, bb = ab + 16384;
        #pragma unroll
        for (int ks = 0; ks < 4; ++ks) {
            uint32_t af[4][4], bfr[4][4];          // single-buffered fragments
            #pragma unroll
            for (int mi = 0; mi < 4; ++mi) {
                int row = wm * 64 + mi * 16 + (lane & 15);
                int kb  = ks * 32 + ((lane & 16) ? 16 : 0);
                LDSM4(af[mi], ab + swz(row, kb));
            }
            #pragma unroll
            for (int p = 0; p < 4; ++p) {
                int row = wn * 64 + p * 16 + (lane & 7) + ((lane & 16) ? 8 : 0);
                int kb  = ks * 32 + ((lane & 8) ? 16 : 0);
                LDSM4(bfr[p], bb + swz(row, kb));
            }
            #pragma unroll
            for (int mi = 0; mi < 4; ++mi)
                #pragma unroll
                for (int p = 0; p < 4; ++p) {
                    MMA16816(c[mi][p*2],   af[mi][0], af[mi][1], af[mi][2], af[mi][3],
                             bfr[p][0], bfr[p][1]);
                    MMA16816(c[mi][p*2+1], af[mi][0], af[mi][1], af[mi][2], af[mi][3],
                             bfr[p][2], bfr[p][3]);
                }
        }
        __syncthreads();
        if (ch + 2 < NCHUNK) load(ch + 2, st);
        if (ch + 1 < NCHUNK) {
            if (ch + 2 < NCHUNK) asm volatile("cp.async.wait_group %0;\n" :: "n"(1));
            else                 asm volatile("cp.async.wait_group 0;\n");
            __syncthreads();
        }
    }

    // ---------------- epilogue ----------------
    const int colb = n0 + wn * 64 + (lane & 3) * 2;
    if (EPI == 1) {
        // proj + window-reverse + shift + residual -> x1 (fp32), then fused LN2 -> m1 (bf16)
        float* redS  = (float*)smc;                 // [2][128]
        float* redSS = redS + 256;
        __syncthreads();
        int lins[4][2];
        #pragma unroll
        for (int mi = 0; mi < 4; ++mi) {
            #pragma unroll
            for (int h = 0; h < 2; ++h) {
                int m = m0 + wm * 64 + mi * 16 + (lane >> 2) + h * 8;
                int w = m / NTOK, n = m % NTOK;
                int dblk = w >> 6, hblk = (w >> 3) & 7, wblk = w & 7;
                int t = n / 49, hh = (n / 7) % 7, ww = n % 7;
                int gd = (dblk * 8 + t + 4) & 15;
                int gh = hblk * 7 + hh + 3; if (gh >= 56) gh -= 56;
                int gx = wblk * 7 + ww + 3; if (gx >= 56) gx -= 56;
                int lin = ((gd * 56 + gh) * 56 + gx) * CC;
                lins[mi][h] = lin;
                float s = 0.f, ss = 0.f;
                #pragma unroll
                for (int ni = 0; ni < 8; ++ni) {
                    int j = colb + ni * 8;
                    float2 e = *(const float2*)(extra + lin + j);
                    float v0 = c[mi][ni][h*2+0] + bias[j]   + e.x;
                    float v1 = c[mi][ni][h*2+1] + bias[j+1] + e.y;
                    *(float2*)((float*)outv + lin + j) = make_float2(v0, v1);
                    c[mi][ni][h*2+0] = v0; c[mi][ni][h*2+1] = v1;
                    s  += v0 + v1;
                    ss += v0 * v0 + v1 * v1;
                }
                s  += __shfl_xor_sync(~0u, s, 1);  s  += __shfl_xor_sync(~0u, s, 2);
                ss += __shfl_xor_sync(~0u, ss, 1); ss += __shfl_xor_sync(~0u, ss, 2);
                if ((lane & 3) == 0) {
                    int rrow = wm * 64 + mi * 16 + (lane >> 2) + h * 8;
                    redS [wn * 128 + rrow] = s;
                    redSS[wn * 128 + rrow] = ss;
                }
            }
        }
        __syncthreads();
        bf16* o2 = (bf16*)out2;
        #pragma unroll
        for (int mi = 0; mi < 4; ++mi) {
            #pragma unroll
            for (int h = 0; h < 2; ++h) {
                int rrow = wm * 64 + mi * 16 + (lane >> 2) + h * 8;
                int lin = lins[mi][h];
                float S  = redS[rrow]  + redS[128 + rrow];
                float SS = redSS[rrow] + redSS[128 + rrow];
                float mu  = S * (1.f / CC);
                float var = SS * (1.f / CC) - mu * mu;
                float rs  = rsqrtf(var + 1e-5f);
                #pragma unroll
                for (int ni = 0; ni < 8; ++ni) {
                    int j = colb + ni * 8;
                    float2 gwv = *(const float2*)(lnw + j);
                    float2 gbv = *(const float2*)(lnb + j);
                    float v0 = (c[mi][ni][h*2+0] - mu) * rs * gwv.x + gbv.x;
                    float v1 = (c[mi][ni][h*2+1] - mu) * rs * gwv.y + gbv.y;
                    *(uint32_t*)(o2 + lin + j) = packbf(v0, v1);
                }
            }
        }
        return;
    }
    #pragma unroll
    for (int mi = 0; mi < 4; ++mi) {
        #pragma unroll
        for (int h = 0; h < 2; ++h) {
            int m = m0 + wm * 64 + mi * 16 + (lane >> 2) + h * 8;
            if (EPI == 0) {                 // QKV scatter (+scale q by QSCALE) -> bf16
                int w = m / NTOK, n = m % NTOK;
                bf16* out = (bf16*)outv;
                #pragma unroll
                for (int ni = 0; ni < 8; ++ni) {
                    int j = colb + ni * 8;
                    float v0 = c[mi][ni][h*2+0] + bias[j];
                    float v1 = c[mi][ni][h*2+1] + bias[j+1];
                    int sel = j >> 7, hd = (j >> 5) & 3, dch = j & 31;
                    if (sel == 0) { v0 *= QSCALE; v1 *= QSCALE; }
                    *(uint32_t*)(out + (size_t)(((sel*NWIN + w)*NHEAD + hd)*NTOK + n)*HEADD + dch)
                        = packbf(v0, v1);
                }
            } else if (EPI == 2) {          // FC1 + exact GELU -> bf16
                bf16* out = (bf16*)outv;
                #pragma unroll
                for (int ni = 0; ni < 8; ++ni) {
                    int j = colb + ni * 8;
                    float v0 = c[mi][ni][h*2+0] + bias[j];
                    float v1 = c[mi][ni][h*2+1] + bias[j+1];
                    v0 = 0.5f * v0 * (1.f + erff(v0 * 0.70710678118654752f));
                    v1 = 0.5f * v1 * (1.f + erff(v1 * 0.70710678118654752f));
                    *(uint32_t*)(out + (size_t)m * HIDD + j) = packbf(v0, v1);
                }
            } else {                        // FC2 + residual -> final fp32 out
                float* out = (float*)outv;
                #pragma unroll
                for (int ni = 0; ni < 8; ++ni) {
                    int j = colb + ni * 8;
                    float2 e = *(const float2*)(extra + (size_t)m * CC + j);
                    *(float2*)(out + (size_t)m * CC + j) = make_float2(
                        c[mi][ni][h*2+0] + bias[j]   + e.x,
                        c[mi][ni][h*2+1] + bias[j+1] + e.y);
                }
            }
        }
    }
}

// ---------------- bf16 HMMA attention: R9 (bias pre-loaded into accumulators) ----------------
__global__ void __launch_bounds__(256, 3) attn_mma(const bf16* __restrict__ qkv,
                                                   const float4* __restrict__ btabF,
                                                   bf16* __restrict__ y) {
    const int w = blockIdx.x >> 2, head = blockIdx.x & 3;
    extern __shared__ char sm[];
    const uint32_t smb = (uint32_t)__cvta_generic_to_shared(sm);
    const uint32_t ksb = smb, vsb = smb + 32000;   // 400 rows x 80B each

    const int tid = threadIdx.x, lane = tid & 31, warp = tid >> 5;
    const size_t hw = ((size_t)(w * NHEAD + head)) * NTOK * HEADD;
    const bf16* qb = qkv + hw;
    const bf16* kb = qkv + (size_t)MROWS * CC + hw;
    const bf16* vb = qkv + 2 * (size_t)MROWS * CC + hw;

    // zero pad rows 392..399 (640 B per buffer)
    for (int i = tid; i < 320; i += 256) {
        int buf = (i >= 160);
        int j = i - buf * 160;
        *(uint32_t*)(sm + buf * 32000 + 392 * 80 + j * 4) = 0u;
    }
    for (int i = tid; i < NTOK * 4; i += 256) {
        int row = i >> 2, off = i & 3;
        cp16(ksb + row * 80 + off * 16, kb + row * 32 + off * 8);
        cp16(vsb + row * 80 + off * 16, vb + row * 32 + off * 8);
    }
    asm volatile("cp.async.commit_group;\n");
    asm volatile("cp.async.wait_group 0;\n");
    __syncthreads();

    const int wtype = ((w >> 6) << 2) | ((((w >> 3) & 7) == 7) ? 2 : 0) | (((w & 7) == 7) ? 1 : 0);
    const float4* btb = btabF + ((size_t)(wtype * NHEAD + head) * 625) * 64 + lane;

    const int r  = lane >> 2, c2 = (lane & 3) * 2;
    const int lrow = (lane & 7) + ((lane & 16) ? 8 : 0);
    const int loff = (lane & 8) ? 16 : 0;

    for (int mt = warp; mt < 25; mt += 8) {
        const int m0r = mt * 16;
        uint32_t qa[2][4];
        #pragma unroll
        for (int kt = 0; kt < 2; ++kt) {
            qa[kt][0] = *(const uint32_t*)(qb + (m0r + r    ) * 32 + kt * 16 +     c2);
            qa[kt][1] = *(const uint32_t*)(qb + (m0r + r + 8) * 32 + kt * 16 +     c2);
            qa[kt][2] = *(const uint32_t*)(qb + (m0r + r    ) * 32 + kt * 16 + 8 + c2);
            qa[kt][3] = *(const uint32_t*)(qb + (m0r + r + 8) * 32 + kt * 16 + 8 + c2);
        }
        float oc[4][4];
        #pragma unroll
        for (int a = 0; a < 4; ++a)
            #pragma unroll
            for (int e = 0; e < 4; ++e) oc[a][e] = 0.f;
        float rs0 = 0.f, rs1 = 0.f;

        const float4* bt = btb + (size_t)(mt * 25) * 64;
        uint32_t kadr = ksb + lrow * 80 + loff;
        uint32_t vadr = vsb + lrow * 80 + loff;

        #pragma unroll 2
        for (int np = 0; np < 25; ++np) {
            float4 bA = bt[0];                       // coalesced 512B warp loads
            float4 bB = bt[32];
            uint32_t kf0[4], kf1[4];
            LDSM4(kf0, kadr);
            LDSM4(kf1, kadr + 32);
            // accumulators INITIALIZED with bias*log2e — no post-hoc adds
            float sA[4] = {bA.x, bA.y, bA.z, bA.w};
            float sB[4] = {bB.x, bB.y, bB.z, bB.w};
            MMA16816(sA, qa[0][0], qa[0][1], qa[0][2], qa[0][3], kf0[0], kf0[1]);
            MMA16816(sA, qa[1][0], qa[1][1], qa[1][2], qa[1][3], kf1[0], kf1[1]);
            MMA16816(sB, qa[0][0], qa[0][1], qa[0][2], qa[0][3], kf0[2], kf0[3]);
            MMA16816(sB, qa[1][0], qa[1][1], qa[1][2], qa[1][3], kf1[2], kf1[3]);
            float e0 = ex2f(sA[0]), e1 = ex2f(sA[1]);
            float e2 = ex2f(sA[2]), e3 = ex2f(sA[3]);
            float e4 = ex2f(sB[0]), e5 = ex2f(sB[1]);
            float e6 = ex2f(sB[2]), e7 = ex2f(sB[3]);
            rs0 += (e0 + e1) + (e4 + e5);
            rs1 += (e2 + e3) + (e6 + e7);
            uint32_t pa0 = packbf(e0, e1), pa1 = packbf(e2, e3);
            uint32_t pa2 = packbf(e4, e5), pa3 = packbf(e6, e7);
            uint32_t vf0[4], vf1[4];
            LDSM4T(vf0, vadr);
            LDSM4T(vf1, vadr + 32);
            MMA16816(oc[0], pa0, pa1, pa2, pa3, vf0[0], vf0[2]);
            MMA16816(oc[1], pa0, pa1, pa2, pa3, vf0[1], vf0[3]);
            MMA16816(oc[2], pa0, pa1, pa2, pa3, vf1[0], vf1[2]);
            MMA16816(oc[3], pa0, pa1, pa2, pa3, vf1[1], vf1[3]);
            kadr += 16 * 80;
            vadr += 16 * 80;
            bt   += 64;
        }
        rs0 += __shfl_xor_sync(~0u, rs0, 1); rs0 += __shfl_xor_sync(~0u, rs0, 2);
        rs1 += __shfl_xor_sync(~0u, rs1, 1); rs1 += __shfl_xor_sync(~0u, rs1, 2);
        float i0 = 1.f / rs0, i1 = 1.f / rs1;
        {
            size_t yb = ((size_t)(w * NTOK + m0r + r)) * CC + head * HEADD + c2;
            #pragma unroll
            for (int dt = 0; dt < 4; ++dt)
                *(uint32_t*)(y + yb + dt * 8) = packbf(oc[dt][0] * i0, oc[dt][1] * i0);
        }
        if (m0r + r + 8 < NTOK) {
            size_t yb = ((size_t)(w * NTOK + m0r + r + 8)) * CC + head * HEADD + c2;
            #pragma unroll
            for (int dt = 0; dt < 4; ++dt)
                *(uint32_t*)(y + yb + dt * 8) = packbf(oc[dt][2] * i1, oc[dt][3] * i1);
        }
    }
}

// ---------------- launch ----------------
extern "C" void kernel_launch(void* const* d_in, const int* in_sizes, int n_in,
                              void* d_out, int out_size) {
    (void)in_sizes; (void)n_in; (void)out_size;
    const float* x     = (const float*)d_in[0];
    const float* n1w   = (const float*)d_in[1];
    const float* n1b   = (const float*)d_in[2];
    const float* qkvw  = (const float*)d_in[3];
    const float* qkvb  = (const float*)d_in[4];
    const float* relt  = (const float*)d_in[5];
    const float* projw = (const float*)d_in[6];
    const float* projb = (const float*)d_in[7];
    const float* n2w   = (const float*)d_in[8];
    const float* n2b   = (const float*)d_in[9];
    const float* fc1w  = (const float*)d_in[10];
    const float* fc1b  = (const float*)d_in[11];
    const float* fc2w  = (const float*)d_in[12];
    const float* fc2b  = (const float*)d_in[13];

    bf16 *win, *qkvB, *yB, *m1, *hid, *wb;
    float *x1;
    float4 *btabF;
    cudaGetSymbolAddress((void**)&win,   g_win);
    cudaGetSymbolAddress((void**)&qkvB,  g_qkv);
    cudaGetSymbolAddress((void**)&yB,    g_y);
    cudaGetSymbolAddress((void**)&x1,    g_x1);
    cudaGetSymbolAddress((void**)&m1,    g_m1);
    cudaGetSymbolAddress((void**)&hid,   g_hid);
    cudaGetSymbolAddress((void**)&wb,    g_wb);
    cudaGetSymbolAddress((void**)&btabF, g_btabF);

    cudaFuncSetAttribute(attn_mma, cudaFuncAttributeMaxDynamicSharedMemorySize, SMEM_ATT);
    cudaFuncSetAttribute(attn_mma, cudaFuncAttributePreferredSharedMemoryCarveout, 100);
    cudaFuncSetAttribute(mgemm2<0,384,128>, cudaFuncAttributeMaxDynamicSharedMemorySize, SMEM_G2);
    cudaFuncSetAttribute(mgemm2<1,128,128>, cudaFuncAttributeMaxDynamicSharedMemorySize, SMEM_G2);
    cudaFuncSetAttribute(mgemm2<2,512,128>, cudaFuncAttributeMaxDynamicSharedMemorySize, SMEM_G2);
    cudaFuncSetAttribute(mgemm2<3,128,512>, cudaFuncAttributeMaxDynamicSharedMemorySize, SMEM_G2);
    cudaFuncSetAttribute(mgemm2<0,384,128>, cudaFuncAttributePreferredSharedMemoryCarveout, 100);
    cudaFuncSetAttribute(mgemm2<1,128,128>, cudaFuncAttributePreferredSharedMemoryCarveout, 100);
    cudaFuncSetAttribute(mgemm2<2,512,128>, cudaFuncAttributePreferredSharedMemoryCarveout, 100);
    cudaFuncSetAttribute(mgemm2<3,128,512>, cudaFuncAttributePreferredSharedMemoryCarveout, 100);

    prep_kernel<<<192 + 2500, 256>>>(qkvw, projw, fc1w, fc2w, wb, relt, btabF);
    ln_kernel<<<MROWS / 8, 256>>>(x, n1w, n1b, win);
    mgemm2<0, 384, 128><<<dim3(392, 3), 128, SMEM_G2>>>(win, wb, qkvb,
        nullptr, nullptr, nullptr, nullptr, qkvB);
    attn_mma<<<NWIN * NHEAD, 256, SMEM_ATT>>>(qkvB, btabF, yB);
    mgemm2<1, 128, 128><<<dim3(392, 1), 128, SMEM_G2>>>(yB, wb + 49152, projb,
        x, n2w, n2b, m1, x1);
    mgemm2<2, 512, 128><<<dim3(392, 4), 128, SMEM_G2>>>(m1, wb + 65536, fc1b,
        nullptr, nullptr, nullptr, nullptr, hid);
    mgemm2<3, 128, 512><<<dim3(392, 1), 128, SMEM_G2>>>(hid, wb + 131072, fc2b,
        x1, nullptr, nullptr, nullptr, (float*)d_out);
}

// round 13
// speedup vs baseline: 1.0643x; 1.0643x over previous
#include <cuda_runtime.h>
#include <cuda_bf16.h>
#include <math.h>
#include <stdint.h>

// ---------------- problem constants ----------------
#define CC      128
#define NHEAD   4
#define HEADD   32
#define NTOK    392
#define NPAD    400
#define NWIN    128
#define MROWS   50176
#define HIDD    512
#define SCALE_Q 0.17677669529663687f
#define LOG2E   1.4426950408889634f
#define QSCALE  (0.25503489337494845f)   // SCALE_Q * LOG2E
#define SMEM_ATT  51200     // attention: Ks + Vs, 400 rows x 64B (SW64)
#define SMEM_G2   65536     // gemm: 2 stages x (A 16KB + B 16KB)

typedef __nv_bfloat16 bf16;

// ---------------- scratch (device globals) ----------------
__device__ __align__(16) bf16  g_win[MROWS * CC];
__device__ __align__(16) bf16  g_qkv[3 * MROWS * CC];   // bf16 (sel,w,head,n,d)
__device__ __align__(16) bf16  g_y[MROWS * CC];
__device__ __align__(16) float g_x1[MROWS * CC];
__device__ __align__(16) bf16  g_m1[MROWS * CC];
__device__ __align__(16) bf16  g_hid[MROWS * HIDD];
__device__ __align__(16) bf16  g_wb[196608];
__device__ __align__(16) float4 g_btabF[32 * 625 * 2 * 32]; // fp32 accumulator-frag bias*log2e

// ---------------- asm helpers ----------------
__device__ __forceinline__ void cp16(uint32_t dst, const void* src) {
    asm volatile("cp.async.cg.shared.global [%0], [%1], 16;\n" :: "r"(dst), "l"(src));
}
__device__ __forceinline__ uint32_t swz(int row, int kb) {        // SW128 (gemm)
    return (uint32_t)((row << 7) + (kb ^ ((row & 7) << 4)));
}
__device__ __forceinline__ uint32_t swz64(uint32_t off) {         // SW64 (attention)
    return off ^ ((off >> 3) & 0x30);
}
__device__ __forceinline__ float ex2f(float x) {
    float y;
    asm("ex2.approx.ftz.f32 %0, %1;" : "=f"(y) : "f"(x));
    return y;
}
#define LDSM4(R, addr) \
    asm volatile("ldmatrix.sync.aligned.m8n8.x4.shared.b16 {%0,%1,%2,%3}, [%4];\n" \
        : "=r"((R)[0]), "=r"((R)[1]), "=r"((R)[2]), "=r"((R)[3]) : "r"(addr))
#define LDSM4T(R, addr) \
    asm volatile("ldmatrix.sync.aligned.m8n8.x4.trans.shared.b16 {%0,%1,%2,%3}, [%4];\n" \
        : "=r"((R)[0]), "=r"((R)[1]), "=r"((R)[2]), "=r"((R)[3]) : "r"(addr))
#define MMA16816(d, a0,a1,a2,a3, b0,b1) \
    asm volatile("mma.sync.aligned.m16n8k16.row.col.f32.bf16.bf16.f32 " \
        "{%0,%1,%2,%3}, {%4,%5,%6,%7}, {%8,%9}, {%0,%1,%2,%3};\n" \
        : "+f"((d)[0]), "+f"((d)[1]), "+f"((d)[2]), "+f"((d)[3]) \
        : "r"(a0), "r"(a1), "r"(a2), "r"(a3), "r"(b0), "r"(b1))

__device__ __forceinline__ uint32_t packbf(float a, float b) {
    __nv_bfloat162 p = __floats2bfloat162_rn(a, b);
    return *(uint32_t*)&p;
}

// ---------------- prep + LN1 merged: weights cvt, bias table, LN1+shift+partition ----------------
__global__ void __launch_bounds__(256) prep_kernel(
        const float* __restrict__ s0, const float* __restrict__ s1,
        const float* __restrict__ s2, const float* __restrict__ s3,
        bf16* __restrict__ wb,
        const float* __restrict__ relt, float4* __restrict__ btabF,
        const float* __restrict__ x,
        const float* __restrict__ n1w, const float* __restrict__ n1b,
        bf16* __restrict__ win) {
    int b = blockIdx.x;
    if (b < 192) {                          // weight conversion: 49152 float4
        int i = b * 256 + threadIdx.x;
        const float* s; int off;
        if (i < 12288)      { s = s0; off = 0; }
        else if (i < 16384) { s = s1; off = 12288; }
        else if (i < 32768) { s = s2; off = 16384; }
        else                { s = s3; off = 32768; }
        float4 v = ((const float4*)s)[i - off];
        ((uint2*)wb)[i] = make_uint2(packbf(v.x, v.y), packbf(v.z, v.w));
        return;
    }
    if (b < 192 + 2500) {
        // bias table (pre-scaled by LOG2E), fp32 accumulator-fragment layout
        int gid = (b - 192) * 256 + threadIdx.x;        // 0 .. 640000-1
        int lane = gid & 31;
        int t    = gid >> 5;                            // 0..19999
        int tile = t % 625;
        int hw_  = t / 625;
        int head = hw_ & 3, wt = hw_ >> 2;
        int mt = tile / 25, np = tile % 25;
        int r = lane >> 2, cb = (lane & 3) * 2;
        float vv[2][4];
        #pragma unroll
        for (int ri = 0; ri < 2; ++ri) {
            int row = mt * 16 + r + ri * 8;
            bool rowpad = row >= NTOK;
            int tn = 0, hn = 0, wn_ = 0, regn = 0;
            if (!rowpad) {
                tn = row / 49; hn = (row / 7) % 7; wn_ = row % 7;
                regn = ((wt & 4) ? (tn  < 4 ? 1 : 2) : 0) * 9
                     + ((wt & 2) ? (hn  < 4 ? 1 : 2) : 0) * 3
                     + ((wt & 1) ? (wn_ < 4 ? 1 : 2) : 0);
            }
            #pragma unroll
            for (int ci = 0; ci < 4; ++ci) {
                int col = np * 16 + cb + (ci & 1) + (ci >> 1) * 8;
                float v;
                if (col >= NTOK)      v = -100.f * LOG2E;
                else if (rowpad)      v = 0.f;
                else {
                    int tm = col / 49, hm = (col / 7) % 7, wm_ = col % 7;
                    int regm = ((wt & 4) ? (tm  < 4 ? 1 : 2) : 0) * 9
                             + ((wt & 2) ? (hm  < 4 ? 1 : 2) : 0) * 3
                             + ((wt & 1) ? (wm_ < 4 ? 1 : 2) : 0);
                    int idx = (tn - tm + 7) * 169 + (hn - hm + 6) * 13 + (wn_ - wm_ + 6);
                    float bb = relt[idx * NHEAD + head];
                    v = ((regn == regm) ? bb : bb - 100.f) * LOG2E;
                }
                vv[ri][ci] = v;
            }
        }
        btabF[((size_t)t * 2 + 0) * 32 + lane] = make_float4(vv[0][0], vv[0][1], vv[1][0], vv[1][1]);
        btabF[((size_t)t * 2 + 1) * 32 + lane] = make_float4(vv[0][2], vv[0][3], vv[1][2], vv[1][3]);
        return;
    }
    // LN1 + cyclic shift + window partition (bf16 out)
    int row  = (b - 192 - 2500) * 8 + (threadIdx.x >> 5);
    int lane = threadIdx.x & 31;
    int w = row / NTOK, n = row % NTOK;
    int dblk = w >> 6, hblk = (w >> 3) & 7, wblk = w & 7;
    int t = n / 49, hh = (n / 7) % 7, ww = n % 7;
    int gd = (dblk * 8 + t + 4) & 15;
    int gh = hblk * 7 + hh + 3; if (gh >= 56) gh -= 56;
    int gx = wblk * 7 + ww + 3; if (gx >= 56) gx -= 56;
    int src = (gd * 56 + gh) * 56 + gx;
    float4 v = *(const float4*)(x + (size_t)src * CC + lane * 4);
    float s  = v.x + v.y + v.z + v.w;
    float ss = v.x*v.x + v.y*v.y + v.z*v.z + v.w*v.w;
    #pragma unroll
    for (int o = 16; o; o >>= 1) {
        s  += __shfl_xor_sync(~0u, s,  o);
        ss += __shfl_xor_sync(~0u, ss, o);
    }
    float mu  = s * (1.f / CC);
    float var = ss * (1.f / CC) - mu * mu;
    float rs  = rsqrtf(var + 1e-5f);
    float4 gwv = *(const float4*)(n1w + lane * 4);
    float4 gbv = *(const float4*)(n1b + lane * 4);
    *(uint2*)(win + (size_t)row * CC + lane * 4) = make_uint2(
        packbf((v.x - mu) * rs * gwv.x + gbv.x, (v.y - mu) * rs * gwv.y + gbv.y),
        packbf((v.z - mu) * rs * gwv.z + gbv.z, (v.w - mu) * rs * gwv.w + gbv.w));
}

// ---------------- bf16 HMMA GEMM: R9 config (128x128 CTA, 4 warps @ 64x64, dbl-buffered frags)
// EPI: 0=QKV scatter  1=proj+reverse+residual+LN2(fused)  2=FC1+GELU  3=FC2+residual
template<int EPI, int ND, int KK>
__global__ void __launch_bounds__(128) mgemm2(const bf16* __restrict__ A,
                                              const bf16* __restrict__ B,
                                              const float* __restrict__ bias,
                                              const float* __restrict__ extra,
                                              const float* __restrict__ lnw,
                                              const float* __restrict__ lnb,
                                              void* __restrict__ out2,
                                              void* __restrict__ outv) {
    extern __shared__ char smc[];
    const uint32_t smb = (uint32_t)__cvta_generic_to_shared(smc);
    const int tid = threadIdx.x, lane = tid & 31, warp = tid >> 5;
    const int wm = warp >> 1, wn = warp & 1;          // 2x2 warp grid, 64x64 tiles
    const int m0 = blockIdx.x * 128, n0 = blockIdx.y * 128;
    constexpr int NCHUNK = KK / 64;

    float c[4][8][4];
    #pragma unroll
    for (int a = 0; a < 4; ++a)
        #pragma unroll
        for (int b = 0; b < 8; ++b)
            #pragma unroll
            for (int e = 0; e < 4; ++e) c[a][b][e] = 0.f;

    auto load = [&](int ch, int st) {
        uint32_t ab = smb + st * 32768, bb = ab + 16384;
        const char* Ap = (const char*)(A + (size_t)m0 * KK + ch * 64);
        const char* Bp = (const char*)(B + (size_t)n0 * KK + ch * 64);
        #pragma unroll
        for (int i = 0; i < 8; ++i) {
            int cid = tid + i * 128;
            int row = cid >> 3, kb = (cid & 7) * 16;
            cp16(ab + swz(row, kb), Ap + (size_t)row * (KK * 2) + kb);
            cp16(bb + swz(row, kb), Bp + (size_t)row * (KK * 2) + kb);
        }
        asm volatile("cp.async.commit_group;\n");
    };

    load(0, 0);
    if (NCHUNK > 1) load(1, 1);
    asm volatile("cp.async.wait_group %0;\n" :: "n"(1));
    if (NCHUNK == 1) asm volatile("cp.async.wait_group 0;\n");
    __syncthreads();

    #pragma unroll 1
    for (int ch = 0; ch < NCHUNK; ++ch) {
        const int st = ch & 1;
        const uint32_t ab = smb + st * 32768, bb = ab + 16384;
        uint32_t af[2][4][4], bfr[2][4][4];
        auto ldf = [&](int ks, int u) {
            #pragma unroll
            for (int mi = 0; mi < 4; ++mi) {
                int row = wm * 64 + mi * 16 + (lane & 15);
                int kb  = ks * 32 + ((lane & 16) ? 16 : 0);
                LDSM4(af[u][mi], ab + swz(row, kb));
            }
            #pragma unroll
            for (int p = 0; p < 4; ++p) {
                int row = wn * 64 + p * 16 + (lane & 7) + ((lane & 16) ? 8 : 0);
                int kb  = ks * 32 + ((lane & 8) ? 16 : 0);
                LDSM4(bfr[u][p], bb + swz(row, kb));
            }
        };
        ldf(0, 0);
        #pragma unroll
        for (int ks = 0; ks < 4; ++ks) {
            if (ks < 3) ldf(ks + 1, (ks + 1) & 1);
            const int u = ks & 1;
            #pragma unroll
            for (int mi = 0; mi < 4; ++mi)
                #pragma unroll
                for (int p = 0; p < 4; ++p) {
                    MMA16816(c[mi][p*2],   af[u][mi][0], af[u][mi][1], af[u][mi][2], af[u][mi][3],
                             bfr[u][p][0], bfr[u][p][1]);
                    MMA16816(c[mi][p*2+1], af[u][mi][0], af[u][mi][1], af[u][mi][2], af[u][mi][3],
                             bfr[u][p][2], bfr[u][p][3]);
                }
        }
        __syncthreads();
        if (ch + 2 < NCHUNK) load(ch + 2, st);
        if (ch + 1 < NCHUNK) {
            if (ch + 2 < NCHUNK) asm volatile("cp.async.wait_group %0;\n" :: "n"(1));
            else                 asm volatile("cp.async.wait_group 0;\n");
            __syncthreads();
        }
    }

    // ---------------- epilogue ----------------
    const int colb = n0 + wn * 64 + (lane & 3) * 2;
    if (EPI == 1) {
        // proj + window-reverse + shift + residual -> x1 (fp32), then fused LN2 -> m1 (bf16)
        float* redS  = (float*)smc;                 // [2][128]
        float* redSS = redS + 256;
        __syncthreads();
        int lins[4][2];
        #pragma unroll
        for (int mi = 0; mi < 4; ++mi) {
            #pragma unroll
            for (int h = 0; h < 2; ++h) {
                int m = m0 + wm * 64 + mi * 16 + (lane >> 2) + h * 8;
                int w = m / NTOK, n = m % NTOK;
                int dblk = w >> 6, hblk = (w >> 3) & 7, wblk = w & 7;
                int t = n / 49, hh = (n / 7) % 7, ww = n % 7;
                int gd = (dblk * 8 + t + 4) & 15;
                int gh = hblk * 7 + hh + 3; if (gh >= 56) gh -= 56;
                int gx = wblk * 7 + ww + 3; if (gx >= 56) gx -= 56;
                int lin = ((gd * 56 + gh) * 56 + gx) * CC;
                lins[mi][h] = lin;
                float s = 0.f, ss = 0.f;
                #pragma unroll
                for (int ni = 0; ni < 8; ++ni) {
                    int j = colb + ni * 8;
                    float2 e = *(const float2*)(extra + lin + j);
                    float v0 = c[mi][ni][h*2+0] + bias[j]   + e.x;
                    float v1 = c[mi][ni][h*2+1] + bias[j+1] + e.y;
                    *(float2*)((float*)outv + lin + j) = make_float2(v0, v1);
                    c[mi][ni][h*2+0] = v0; c[mi][ni][h*2+1] = v1;
                    s  += v0 + v1;
                    ss += v0 * v0 + v1 * v1;
                }
                s  += __shfl_xor_sync(~0u, s, 1);  s  += __shfl_xor_sync(~0u, s, 2);
                ss += __shfl_xor_sync(~0u, ss, 1); ss += __shfl_xor_sync(~0u, ss, 2);
                if ((lane & 3) == 0) {
                    int rrow = wm * 64 + mi * 16 + (lane >> 2) + h * 8;
                    redS [wn * 128 + rrow] = s;
                    redSS[wn * 128 + rrow] = ss;
                }
            }
        }
        __syncthreads();
        bf16* o2 = (bf16*)out2;
        #pragma unroll
        for (int mi = 0; mi < 4; ++mi) {
            #pragma unroll
            for (int h = 0; h < 2; ++h) {
                int rrow = wm * 64 + mi * 16 + (lane >> 2) + h * 8;
                int lin = lins[mi][h];
                float S  = redS[rrow]  + redS[128 + rrow];
                float SS = redSS[rrow] + redSS[128 + rrow];
                float mu  = S * (1.f / CC);
                float var = SS * (1.f / CC) - mu * mu;
                float rs  = rsqrtf(var + 1e-5f);
                #pragma unroll
                for (int ni = 0; ni < 8; ++ni) {
                    int j = colb + ni * 8;
                    float2 gwv = *(const float2*)(lnw + j);
                    float2 gbv = *(const float2*)(lnb + j);
                    float v0 = (c[mi][ni][h*2+0] - mu) * rs * gwv.x + gbv.x;
                    float v1 = (c[mi][ni][h*2+1] - mu) * rs * gwv.y + gbv.y;
                    *(uint32_t*)(o2 + lin + j) = packbf(v0, v1);
                }
            }
        }
        return;
    }
    #pragma unroll
    for (int mi = 0; mi < 4; ++mi) {
        #pragma unroll
        for (int h = 0; h < 2; ++h) {
            int m = m0 + wm * 64 + mi * 16 + (lane >> 2) + h * 8;
            if (EPI == 0) {                 // QKV scatter (+scale q by QSCALE) -> bf16
                int w = m / NTOK, n = m % NTOK;
                bf16* out = (bf16*)outv;
                #pragma unroll
                for (int ni = 0; ni < 8; ++ni) {
                    int j = colb + ni * 8;
                    float v0 = c[mi][ni][h*2+0] + bias[j];
                    float v1 = c[mi][ni][h*2+1] + bias[j+1];
                    int sel = j >> 7, hd = (j >> 5) & 3, dch = j & 31;
                    if (sel == 0) { v0 *= QSCALE; v1 *= QSCALE; }
                    *(uint32_t*)(out + (size_t)(((sel*NWIN + w)*NHEAD + hd)*NTOK + n)*HEADD + dch)
                        = packbf(v0, v1);
                }
            } else if (EPI == 2) {          // FC1 + exact GELU -> bf16
                bf16* out = (bf16*)outv;
                #pragma unroll
                for (int ni = 0; ni < 8; ++ni) {
                    int j = colb + ni * 8;
                    float v0 = c[mi][ni][h*2+0] + bias[j];
                    float v1 = c[mi][ni][h*2+1] + bias[j+1];
                    v0 = 0.5f * v0 * (1.f + erff(v0 * 0.70710678118654752f));
                    v1 = 0.5f * v1 * (1.f + erff(v1 * 0.70710678118654752f));
                    *(uint32_t*)(out + (size_t)m * HIDD + j) = packbf(v0, v1);
                }
            } else {                        // FC2 + residual -> final fp32 out
                float* out = (float*)outv;
                #pragma unroll
                for (int ni = 0; ni < 8; ++ni) {
                    int j = colb + ni * 8;
                    float2 e = *(const float2*)(extra + (size_t)m * CC + j);
                    *(float2*)(out + (size_t)m * CC + j) = make_float2(
                        c[mi][ni][h*2+0] + bias[j]   + e.x,
                        c[mi][ni][h*2+1] + bias[j+1] + e.y);
                }
            }
        }
    }
}

// ---------------- bf16 HMMA attention: SW64 rows, 4 CTAs/SM target, bias-in-accumulator ----------------
__global__ void __launch_bounds__(256, 4) attn_mma(const bf16* __restrict__ qkv,
                                                   const float4* __restrict__ btabF,
                                                   bf16* __restrict__ y) {
    const int w = blockIdx.x >> 2, head = blockIdx.x & 3;
    extern __shared__ char sm[];
    const uint32_t smb = (uint32_t)__cvta_generic_to_shared(sm);
    const uint32_t ksb = smb, vsb = smb + 25600;   // 400 rows x 64B each (SW64)

    const int tid = threadIdx.x, lane = tid & 31, warp = tid >> 5;
    const size_t hw = ((size_t)(w * NHEAD + head)) * NTOK * HEADD;
    const bf16* qb = qkv + hw;
    const bf16* kb = qkv + (size_t)MROWS * CC + hw;
    const bf16* vb = qkv + 2 * (size_t)MROWS * CC + hw;

    // zero pad rows 392..399 (512 B per buffer; SW64 swizzle is closed within each 64B row)
    {
        int i = tid;                                // 256 threads, 256 words
        int buf = (i >= 128);
        int j = i - buf * 128;
        *(uint32_t*)(sm + buf * 25600 + 392 * 64 + j * 4) = 0u;
    }
    // stage K,V via cp.async into SW64 layout
    for (int i = tid; i < NTOK * 4; i += 256) {
        int row = i >> 2, ch = i & 3;
        uint32_t s = swz64((uint32_t)(row * 64 + ch * 16));
        cp16(ksb + s, kb + row * 32 + ch * 8);
        cp16(vsb + s, vb + row * 32 + ch * 8);
    }
    asm volatile("cp.async.commit_group;\n");
    asm volatile("cp.async.wait_group 0;\n");
    __syncthreads();

    const int wtype = ((w >> 6) << 2) | ((((w >> 3) & 7) == 7) ? 2 : 0) | (((w & 7) == 7) ? 1 : 0);
    const float4* btb = btabF + ((size_t)(wtype * NHEAD + head) * 625) * 64 + lane;

    const int r  = lane >> 2, c2 = (lane & 3) * 2;
    const int lrow = (lane & 7) + ((lane & 16) ? 8 : 0);
    const int loff = (lane & 8) ? 16 : 0;
    // base swizzled offset; per-np increment is exactly +1024 (bits 7-8 of the
    // pre-swizzle address don't depend on np), and the +32B partner is s^32
    // (bit 5 of the pre-swizzle address is 0).
    const uint32_t s0 = swz64((uint32_t)(lrow * 64 + loff));

    for (int mt = warp; mt < 25; mt += 8) {
        const int m0r = mt * 16;
        uint32_t qa[2][4];
        #pragma unroll
        for (int kt = 0; kt < 2; ++kt) {
            qa[kt][0] = *(const uint32_t*)(qb + (m0r + r    ) * 32 + kt * 16 +     c2);
            qa[kt][1] = *(const uint32_t*)(qb + (m0r + r + 8) * 32 + kt * 16 +     c2);
            qa[kt][2] = *(const uint32_t*)(qb + (m0r + r    ) * 32 + kt * 16 + 8 + c2);
            qa[kt][3] = *(const uint32_t*)(qb + (m0r + r + 8) * 32 + kt * 16 + 8 + c2);
        }
        float oc[4][4];
        #pragma unroll
        for (int a = 0; a < 4; ++a)
            #pragma unroll
            for (int e = 0; e < 4; ++e) oc[a][e] = 0.f;
        float rs0 = 0.f, rs1 = 0.f;

        const float4* bt = btb + (size_t)(mt * 25) * 64;
        uint32_t ka0 = ksb + s0, ka1 = ksb + (s0 ^ 32u);
        uint32_t va0 = vsb + s0, va1 = vsb + (s0 ^ 32u);

        #pragma unroll 1
        for (int np = 0; np < 25; ++np) {
            float4 bA = bt[0];                       // coalesced 512B warp loads
            float4 bB = bt[32];
            uint32_t kf0[4], kf1[4];
            LDSM4(kf0, ka0);
            LDSM4(kf1, ka1);
            // accumulators INITIALIZED with bias*log2e — no post-hoc adds
            float sA[4] = {bA.x, bA.y, bA.z, bA.w};
            float sB[4] = {bB.x, bB.y, bB.z, bB.w};
            MMA16816(sA, qa[0][0], qa[0][1], qa[0][2], qa[0][3], kf0[0], kf0[1]);
            MMA16816(sA, qa[1][0], qa[1][1], qa[1][2], qa[1][3], kf1[0], kf1[1]);
            MMA16816(sB, qa[0][0], qa[0][1], qa[0][2], qa[0][3], kf0[2], kf0[3]);
            MMA16816(sB, qa[1][0], qa[1][1], qa[1][2], qa[1][3], kf1[2], kf1[3]);
            float e0 = ex2f(sA[0]), e1 = ex2f(sA[1]);
            float e2 = ex2f(sA[2]), e3 = ex2f(sA[3]);
            float e4 = ex2f(sB[0]), e5 = ex2f(sB[1]);
            float e6 = ex2f(sB[2]), e7 = ex2f(sB[3]);
            rs0 += (e0 + e1) + (e4 + e5);
            rs1 += (e2 + e3) + (e6 + e7);
            uint32_t pa0 = packbf(e0, e1), pa1 = packbf(e2, e3);
            uint32_t pa2 = packbf(e4, e5), pa3 = packbf(e6, e7);
            uint32_t vf0[4], vf1[4];
            LDSM4T(vf0, va0);
            LDSM4T(vf1, va1);
            MMA16816(oc[0], pa0, pa1, pa2, pa3, vf0[0], vf0[2]);
            MMA16816(oc[1], pa0, pa1, pa2, pa3, vf0[1], vf0[3]);
            MMA16816(oc[2], pa0, pa1, pa2, pa3, vf1[0], vf1[2]);
            MMA16816(oc[3], pa0, pa1, pa2, pa3, vf1[1], vf1[3]);
            ka0 += 1024; ka1 += 1024;
            va0 += 1024; va1 += 1024;
            bt  += 64;
        }
        rs0 += __shfl_xor_sync(~0u, rs0, 1); rs0 += __shfl_xor_sync(~0u, rs0, 2);
        rs1 += __shfl_xor_sync(~0u, rs1, 1); rs1 += __shfl_xor_sync(~0u, rs1, 2);
        float i0 = 1.f / rs0, i1 = 1.f / rs1;
        {
            size_t yb = ((size_t)(w * NTOK + m0r + r)) * CC + head * HEADD + c2;
            #pragma unroll
            for (int dt = 0; dt < 4; ++dt)
                *(uint32_t*)(y + yb + dt * 8) = packbf(oc[dt][0] * i0, oc[dt][1] * i0);
        }
        if (m0r + r + 8 < NTOK) {
            size_t yb = ((size_t)(w * NTOK + m0r + r + 8)) * CC + head * HEADD + c2;
            #pragma unroll
            for (int dt = 0; dt < 4; ++dt)
                *(uint32_t*)(y + yb + dt * 8) = packbf(oc[dt][2] * i1, oc[dt][3] * i1);
        }
    }
}

// ---------------- launch ----------------
extern "C" void kernel_launch(void* const* d_in, const int* in_sizes, int n_in,
                              void* d_out, int out_size) {
    (void)in_sizes; (void)n_in; (void)out_size;
    const float* x     = (const float*)d_in[0];
    const float* n1w   = (const float*)d_in[1];
    const float* n1b   = (const float*)d_in[2];
    const float* qkvw  = (const float*)d_in[3];
    const float* qkvb  = (const float*)d_in[4];
    const float* relt  = (const float*)d_in[5];
    const float* projw = (const float*)d_in[6];
    const float* projb = (const float*)d_in[7];
    const float* n2w   = (const float*)d_in[8];
    const float* n2b   = (const float*)d_in[9];
    const float* fc1w  = (const float*)d_in[10];
    const float* fc1b  = (const float*)d_in[11];
    const float* fc2w  = (const float*)d_in[12];
    const float* fc2b  = (const float*)d_in[13];

    bf16 *win, *qkvB, *yB, *m1, *hid, *wb;
    float *x1;
    float4 *btabF;
    cudaGetSymbolAddress((void**)&win,   g_win);
    cudaGetSymbolAddress((void**)&qkvB,  g_qkv);
    cudaGetSymbolAddress((void**)&yB,    g_y);
    cudaGetSymbolAddress((void**)&x1,    g_x1);
    cudaGetSymbolAddress((void**)&m1,    g_m1);
    cudaGetSymbolAddress((void**)&hid,   g_hid);
    cudaGetSymbolAddress((void**)&wb,    g_wb);
    cudaGetSymbolAddress((void**)&btabF, g_btabF);

    cudaFuncSetAttribute(attn_mma, cudaFuncAttributeMaxDynamicSharedMemorySize, SMEM_ATT);
    cudaFuncSetAttribute(attn_mma, cudaFuncAttributePreferredSharedMemoryCarveout, 100);
    cudaFuncSetAttribute(mgemm2<0,384,128>, cudaFuncAttributeMaxDynamicSharedMemorySize, SMEM_G2);
    cudaFuncSetAttribute(mgemm2<1,128,128>, cudaFuncAttributeMaxDynamicSharedMemorySize, SMEM_G2);
    cudaFuncSetAttribute(mgemm2<2,512,128>, cudaFuncAttributeMaxDynamicSharedMemorySize, SMEM_G2);
    cudaFuncSetAttribute(mgemm2<3,128,512>, cudaFuncAttributeMaxDynamicSharedMemorySize, SMEM_G2);

    // prep (weights cvt + bias table) + LN1, merged into one launch
    prep_kernel<<<192 + 2500 + MROWS / 8, 256>>>(qkvw, projw, fc1w, fc2w, wb,
                                                 relt, btabF, x, n1w, n1b, win);
    mgemm2<0, 384, 128><<<dim3(392, 3), 128, SMEM_G2>>>(win, wb, qkvb,
        nullptr, nullptr, nullptr, nullptr, qkvB);
    attn_mma<<<NWIN * NHEAD, 256, SMEM_ATT>>>(qkvB, btabF, yB);
    mgemm2<1, 128, 128><<<dim3(392, 1), 128, SMEM_G2>>>(yB, wb + 49152, projb,
        x, n2w, n2b, m1, x1);
    mgemm2<2, 512, 128><<<dim3(392, 4), 128, SMEM_G2>>>(m1, wb + 65536, fc1b,
        nullptr, nullptr, nullptr, nullptr, hid);
    mgemm2<3, 128, 512><<<dim3(392, 1), 128, SMEM_G2>>>(hid, wb + 131072, fc2b,
        x1, nullptr, nullptr, nullptr, (float*)d_out);
}

// round 14
// speedup vs baseline: 1.0690x; 1.0044x over previous
#include <cuda_runtime.h>
#include <cuda_bf16.h>
#include <math.h>
#include <stdint.h>

// ---------------- problem constants ----------------
#define CC      128
#define NHEAD   4
#define HEADD   32
#define NTOK    392
#define NPAD    400
#define NWIN    128
#define MROWS   50176
#define HIDD    512
#define SCALE_Q 0.17677669529663687f
#define LOG2E   1.4426950408889634f
#define QSCALE  (0.25503489337494845f)   // SCALE_Q * LOG2E
#define SMEM_ATT  51200     // attention: Ks + Vs, 400 rows x 64B (SW64)
#define SMEM_G2   65536     // gemm: 2 stages x (A 16KB + B 16KB)

typedef __nv_bfloat16 bf16;

// ---------------- scratch (device globals) ----------------
__device__ __align__(16) bf16  g_win[MROWS * CC];
__device__ __align__(16) bf16  g_qkv[3 * MROWS * CC];   // bf16 (sel,w,head,n,d)
__device__ __align__(16) bf16  g_y[MROWS * CC];
__device__ __align__(16) float g_x1[MROWS * CC];
__device__ __align__(16) bf16  g_m1[MROWS * CC];
__device__ __align__(16) bf16  g_hid[MROWS * HIDD];
__device__ __align__(16) bf16  g_wb[196608];
__device__ __align__(16) float4 g_btabF[32 * 625 * 2 * 32]; // fp32 accumulator-frag bias*log2e

// ---------------- asm helpers ----------------
__device__ __forceinline__ void cp16(uint32_t dst, const void* src) {
    asm volatile("cp.async.cg.shared.global [%0], [%1], 16;\n" :: "r"(dst), "l"(src));
}
__device__ __forceinline__ uint32_t swz(int row, int kb) {        // SW128 (gemm)
    return (uint32_t)((row << 7) + (kb ^ ((row & 7) << 4)));
}
__device__ __forceinline__ uint32_t swz64(uint32_t off) {         // SW64 (attention)
    return off ^ ((off >> 3) & 0x30);
}
__device__ __forceinline__ float ex2f(float x) {
    float y;
    asm("ex2.approx.ftz.f32 %0, %1;" : "=f"(y) : "f"(x));
    return y;
}
#define LDSM4(R, addr) \
    asm volatile("ldmatrix.sync.aligned.m8n8.x4.shared.b16 {%0,%1,%2,%3}, [%4];\n" \
        : "=r"((R)[0]), "=r"((R)[1]), "=r"((R)[2]), "=r"((R)[3]) : "r"(addr))
#define LDSM4T(R, addr) \
    asm volatile("ldmatrix.sync.aligned.m8n8.x4.trans.shared.b16 {%0,%1,%2,%3}, [%4];\n" \
        : "=r"((R)[0]), "=r"((R)[1]), "=r"((R)[2]), "=r"((R)[3]) : "r"(addr))
#define MMA16816(d, a0,a1,a2,a3, b0,b1) \
    asm volatile("mma.sync.aligned.m16n8k16.row.col.f32.bf16.bf16.f32 " \
        "{%0,%1,%2,%3}, {%4,%5,%6,%7}, {%8,%9}, {%0,%1,%2,%3};\n" \
        : "+f"((d)[0]), "+f"((d)[1]), "+f"((d)[2]), "+f"((d)[3]) \
        : "r"(a0), "r"(a1), "r"(a2), "r"(a3), "r"(b0), "r"(b1))

__device__ __forceinline__ uint32_t packbf(float a, float b) {
    __nv_bfloat162 p = __floats2bfloat162_rn(a, b);
    return *(uint32_t*)&p;
}

// ---------------- prep + LN1 merged ----------------
__global__ void __launch_bounds__(256) prep_kernel(
        const float* __restrict__ s0, const float* __restrict__ s1,
        const float* __restrict__ s2, const float* __restrict__ s3,
        bf16* __restrict__ wb,
        const float* __restrict__ relt, float4* __restrict__ btabF,
        const float* __restrict__ x,
        const float* __restrict__ n1w, const float* __restrict__ n1b,
        bf16* __restrict__ win) {
    int b = blockIdx.x;
    if (b < 192) {                          // weight conversion: 49152 float4
        int i = b * 256 + threadIdx.x;
        const float* s; int off;
        if (i < 12288)      { s = s0; off = 0; }
        else if (i < 16384) { s = s1; off = 12288; }
        else if (i < 32768) { s = s2; off = 16384; }
        else                { s = s3; off = 32768; }
        float4 v = ((const float4*)s)[i - off];
        ((uint2*)wb)[i] = make_uint2(packbf(v.x, v.y), packbf(v.z, v.w));
        return;
    }
    if (b < 192 + 2500) {
        int gid = (b - 192) * 256 + threadIdx.x;
        int lane = gid & 31;
        int t    = gid >> 5;
        int tile = t % 625;
        int hw_  = t / 625;
        int head = hw_ & 3, wt = hw_ >> 2;
        int mt = tile / 25, np = tile % 25;
        int r = lane >> 2, cb = (lane & 3) * 2;
        float vv[2][4];
        #pragma unroll
        for (int ri = 0; ri < 2; ++ri) {
            int row = mt * 16 + r + ri * 8;
            bool rowpad = row >= NTOK;
            int tn = 0, hn = 0, wn_ = 0, regn = 0;
            if (!rowpad) {
                tn = row / 49; hn = (row / 7) % 7; wn_ = row % 7;
                regn = ((wt & 4) ? (tn  < 4 ? 1 : 2) : 0) * 9
                     + ((wt & 2) ? (hn  < 4 ? 1 : 2) : 0) * 3
                     + ((wt & 1) ? (wn_ < 4 ? 1 : 2) : 0);
            }
            #pragma unroll
            for (int ci = 0; ci < 4; ++ci) {
                int col = np * 16 + cb + (ci & 1) + (ci >> 1) * 8;
                float v;
                if (col >= NTOK)      v = -100.f * LOG2E;
                else if (rowpad)      v = 0.f;
                else {
                    int tm = col / 49, hm = (col / 7) % 7, wm_ = col % 7;
                    int regm = ((wt & 4) ? (tm  < 4 ? 1 : 2) : 0) * 9
                             + ((wt & 2) ? (hm  < 4 ? 1 : 2) : 0) * 3
                             + ((wt & 1) ? (wm_ < 4 ? 1 : 2) : 0);
                    int idx = (tn - tm + 7) * 169 + (hn - hm + 6) * 13 + (wn_ - wm_ + 6);
                    float bb = relt[idx * NHEAD + head];
                    v = ((regn == regm) ? bb : bb - 100.f) * LOG2E;
                }
                vv[ri][ci] = v;
            }
        }
        btabF[((size_t)t * 2 + 0) * 32 + lane] = make_float4(vv[0][0], vv[0][1], vv[1][0], vv[1][1]);
        btabF[((size_t)t * 2 + 1) * 32 + lane] = make_float4(vv[0][2], vv[0][3], vv[1][2], vv[1][3]);
        return;
    }
    // LN1 + cyclic shift + window partition (bf16 out)
    int row  = (b - 192 - 2500) * 8 + (threadIdx.x >> 5);
    int lane = threadIdx.x & 31;
    int w = row / NTOK, n = row % NTOK;
    int dblk = w >> 6, hblk = (w >> 3) & 7, wblk = w & 7;
    int t = n / 49, hh = (n / 7) % 7, ww = n % 7;
    int gd = (dblk * 8 + t + 4) & 15;
    int gh = hblk * 7 + hh + 3; if (gh >= 56) gh -= 56;
    int gx = wblk * 7 + ww + 3; if (gx >= 56) gx -= 56;
    int src = (gd * 56 + gh) * 56 + gx;
    float4 v = *(const float4*)(x + (size_t)src * CC + lane * 4);
    float s  = v.x + v.y + v.z + v.w;
    float ss = v.x*v.x + v.y*v.y + v.z*v.z + v.w*v.w;
    #pragma unroll
    for (int o = 16; o; o >>= 1) {
        s  += __shfl_xor_sync(~0u, s,  o);
        ss += __shfl_xor_sync(~0u, ss, o);
    }
    float mu  = s * (1.f / CC);
    float var = ss * (1.f / CC) - mu * mu;
    float rs  = rsqrtf(var + 1e-5f);
    float4 gwv = *(const float4*)(n1w + lane * 4);
    float4 gbv = *(const float4*)(n1b + lane * 4);
    *(uint2*)(win + (size_t)row * CC + lane * 4) = make_uint2(
        packbf((v.x - mu) * rs * gwv.x + gbv.x, (v.y - mu) * rs * gwv.y + gbv.y),
        packbf((v.z - mu) * rs * gwv.z + gbv.z, (v.w - mu) * rs * gwv.w + gbv.w));
}

// ---------------- bf16 HMMA GEMM v3: 128x128 CTA, 256 threads, 8 warps @ 64x32 ----------------
// 2x4 warp grid -> ~140 regs -> 8 warps/SM (2/SMSP) for latency hiding.
// EPI: 0=QKV scatter  1=proj+reverse+residual+LN2(fused)  2=FC1+GELU  3=FC2+residual
template<int EPI, int ND, int KK>
__global__ void __launch_bounds__(256) mgemm3(const bf16* __restrict__ A,
                                              const bf16* __restrict__ B,
                                              const float* __restrict__ bias,
                                              const float* __restrict__ extra,
                                              const float* __restrict__ lnw,
                                              const float* __restrict__ lnb,
                                              void* __restrict__ out2,
                                              void* __restrict__ outv) {
    extern __shared__ char smc[];
    const uint32_t smb = (uint32_t)__cvta_generic_to_shared(smc);
    const int tid = threadIdx.x, lane = tid & 31, warp = tid >> 5;
    const int wm = warp >> 2, wn = warp & 3;          // 2x4 warp grid, 64x32 tiles
    const int m0 = blockIdx.x * 128, n0 = blockIdx.y * 128;
    constexpr int NCHUNK = KK / 64;

    float c[4][4][4];
    #pragma unroll
    for (int a = 0; a < 4; ++a)
        #pragma unroll
        for (int b = 0; b < 4; ++b)
            #pragma unroll
            for (int e = 0; e < 4; ++e) c[a][b][e] = 0.f;

    auto load = [&](int ch, int st) {
        uint32_t ab = smb + st * 32768, bb = ab + 16384;
        const char* Ap = (const char*)(A + (size_t)m0 * KK + ch * 64);
        const char* Bp = (const char*)(B + (size_t)n0 * KK + ch * 64);
        #pragma unroll
        for (int i = 0; i < 4; ++i) {
            int cid = tid + i * 256;                   // 1024 chunks per matrix
            int row = cid >> 3, kb = (cid & 7) * 16;
            cp16(ab + swz(row, kb), Ap + (size_t)row * (KK * 2) + kb);
            cp16(bb + swz(row, kb), Bp + (size_t)row * (KK * 2) + kb);
        }
        asm volatile("cp.async.commit_group;\n");
    };

    load(0, 0);
    if (NCHUNK > 1) load(1, 1);
    asm volatile("cp.async.wait_group %0;\n" :: "n"(1));
    if (NCHUNK == 1) asm volatile("cp.async.wait_group 0;\n");
    __syncthreads();

    #pragma unroll 1
    for (int ch = 0; ch < NCHUNK; ++ch) {
        const int st = ch & 1;
        const uint32_t ab = smb + st * 32768, bb = ab + 16384;
        uint32_t af[2][4][4], bfr[2][2][4];
        auto ldf = [&](int ks, int u) {
            #pragma unroll
            for (int mi = 0; mi < 4; ++mi) {
                int row = wm * 64 + mi * 16 + (lane & 15);
                int kb  = ks * 32 + ((lane & 16) ? 16 : 0);
                LDSM4(af[u][mi], ab + swz(row, kb));
            }
            #pragma unroll
            for (int p = 0; p < 2; ++p) {
                int row = wn * 32 + p * 16 + (lane & 7) + ((lane & 16) ? 8 : 0);
                int kb  = ks * 32 + ((lane & 8) ? 16 : 0);
                LDSM4(bfr[u][p], bb + swz(row, kb));
            }
        };
        ldf(0, 0);
        #pragma unroll
        for (int ks = 0; ks < 4; ++ks) {
            if (ks < 3) ldf(ks + 1, (ks + 1) & 1);
            const int u = ks & 1;
            #pragma unroll
            for (int mi = 0; mi < 4; ++mi)
                #pragma unroll
                for (int p = 0; p < 2; ++p) {
                    MMA16816(c[mi][p*2],   af[u][mi][0], af[u][mi][1], af[u][mi][2], af[u][mi][3],
                             bfr[u][p][0], bfr[u][p][1]);
                    MMA16816(c[mi][p*2+1], af[u][mi][0], af[u][mi][1], af[u][mi][2], af[u][mi][3],
                             bfr[u][p][2], bfr[u][p][3]);
                }
        }
        __syncthreads();
        if (ch + 2 < NCHUNK) load(ch + 2, st);
        if (ch + 1 < NCHUNK) {
            if (ch + 2 < NCHUNK) asm volatile("cp.async.wait_group %0;\n" :: "n"(1));
            else                 asm volatile("cp.async.wait_group 0;\n");
            __syncthreads();
        }
    }

    // ---------------- epilogue ----------------
    const int colb = n0 + wn * 32 + (lane & 3) * 2;
    if (EPI == 1) {
        // proj + window-reverse + shift + residual -> x1 (fp32), then fused LN2 -> m1 (bf16)
        float* redS  = (float*)smc;                 // [4][128]
        float* redSS = redS + 512;
        __syncthreads();
        int lins[4][2];
        #pragma unroll
        for (int mi = 0; mi < 4; ++mi) {
            #pragma unroll
            for (int h = 0; h < 2; ++h) {
                int m = m0 + wm * 64 + mi * 16 + (lane >> 2) + h * 8;
                int w = m / NTOK, n = m % NTOK;
                int dblk = w >> 6, hblk = (w >> 3) & 7, wblk = w & 7;
                int t = n / 49, hh = (n / 7) % 7, ww = n % 7;
                int gd = (dblk * 8 + t + 4) & 15;
                int gh = hblk * 7 + hh + 3; if (gh >= 56) gh -= 56;
                int gx = wblk * 7 + ww + 3; if (gx >= 56) gx -= 56;
                int lin = ((gd * 56 + gh) * 56 + gx) * CC;
                lins[mi][h] = lin;
                float s = 0.f, ss = 0.f;
                #pragma unroll
                for (int ni = 0; ni < 4; ++ni) {
                    int j = colb + ni * 8;
                    float2 e = *(const float2*)(extra + lin + j);
                    float v0 = c[mi][ni][h*2+0] + bias[j]   + e.x;
                    float v1 = c[mi][ni][h*2+1] + bias[j+1] + e.y;
                    *(float2*)((float*)outv + lin + j) = make_float2(v0, v1);
                    c[mi][ni][h*2+0] = v0; c[mi][ni][h*2+1] = v1;
                    s  += v0 + v1;
                    ss += v0 * v0 + v1 * v1;
                }
                s  += __shfl_xor_sync(~0u, s, 1);  s  += __shfl_xor_sync(~0u, s, 2);
                ss += __shfl_xor_sync(~0u, ss, 1); ss += __shfl_xor_sync(~0u, ss, 2);
                if ((lane & 3) == 0) {
                    int rrow = wm * 64 + mi * 16 + (lane >> 2) + h * 8;
                    redS [wn * 128 + rrow] = s;
                    redSS[wn * 128 + rrow] = ss;
                }
            }
        }
        __syncthreads();
        bf16* o2 = (bf16*)out2;
        #pragma unroll
        for (int mi = 0; mi < 4; ++mi) {
            #pragma unroll
            for (int h = 0; h < 2; ++h) {
                int rrow = wm * 64 + mi * 16 + (lane >> 2) + h * 8;
                int lin = lins[mi][h];
                float S  = redS[rrow]  + redS[128 + rrow]  + redS[256 + rrow]  + redS[384 + rrow];
                float SS = redSS[rrow] + redSS[128 + rrow] + redSS[256 + rrow] + redSS[384 + rrow];
                float mu  = S * (1.f / CC);
                float var = SS * (1.f / CC) - mu * mu;
                float rs  = rsqrtf(var + 1e-5f);
                #pragma unroll
                for (int ni = 0; ni < 4; ++ni) {
                    int j = colb + ni * 8;
                    float2 gwv = *(const float2*)(lnw + j);
                    float2 gbv = *(const float2*)(lnb + j);
                    float v0 = (c[mi][ni][h*2+0] - mu) * rs * gwv.x + gbv.x;
                    float v1 = (c[mi][ni][h*2+1] - mu) * rs * gwv.y + gbv.y;
                    *(uint32_t*)(o2 + lin + j) = packbf(v0, v1);
                }
            }
        }
        return;
    }
    #pragma unroll
    for (int mi = 0; mi < 4; ++mi) {
        #pragma unroll
        for (int h = 0; h < 2; ++h) {
            int m = m0 + wm * 64 + mi * 16 + (lane >> 2) + h * 8;
            if (EPI == 0) {                 // QKV scatter (+scale q by QSCALE) -> bf16
                int w = m / NTOK, n = m % NTOK;
                bf16* out = (bf16*)outv;
                #pragma unroll
                for (int ni = 0; ni < 4; ++ni) {
                    int j = colb + ni * 8;
                    float v0 = c[mi][ni][h*2+0] + bias[j];
                    float v1 = c[mi][ni][h*2+1] + bias[j+1];
                    int sel = j >> 7, hd = (j >> 5) & 3, dch = j & 31;
                    if (sel == 0) { v0 *= QSCALE; v1 *= QSCALE; }
                    *(uint32_t*)(out + (size_t)(((sel*NWIN + w)*NHEAD + hd)*NTOK + n)*HEADD + dch)
                        = packbf(v0, v1);
                }
            } else if (EPI == 2) {          // FC1 + exact GELU -> bf16
                bf16* out = (bf16*)outv;
                #pragma unroll
                for (int ni = 0; ni < 4; ++ni) {
                    int j = colb + ni * 8;
                    float v0 = c[mi][ni][h*2+0] + bias[j];
                    float v1 = c[mi][ni][h*2+1] + bias[j+1];
                    v0 = 0.5f * v0 * (1.f + erff(v0 * 0.70710678118654752f));
                    v1 = 0.5f * v1 * (1.f + erff(v1 * 0.70710678118654752f));
                    *(uint32_t*)(out + (size_t)m * HIDD + j) = packbf(v0, v1);
                }
            } else {                        // FC2 + residual -> final fp32 out
                float* out = (float*)outv;
                #pragma unroll
                for (int ni = 0; ni < 4; ++ni) {
                    int j = colb + ni * 8;
                    float2 e = *(const float2*)(extra + (size_t)m * CC + j);
                    *(float2*)(out + (size_t)m * CC + j) = make_float2(
                        c[mi][ni][h*2+0] + bias[j]   + e.x,
                        c[mi][ni][h*2+1] + bias[j+1] + e.y);
                }
            }
        }
    }
}

// ---------------- bf16 HMMA attention: R13 (SW64, 4 CTAs/SM, bias-in-accumulator) ----------------
__global__ void __launch_bounds__(256, 4) attn_mma(const bf16* __restrict__ qkv,
                                                   const float4* __restrict__ btabF,
                                                   bf16* __restrict__ y) {
    const int w = blockIdx.x >> 2, head = blockIdx.x & 3;
    extern __shared__ char sm[];
    const uint32_t smb = (uint32_t)__cvta_generic_to_shared(sm);
    const uint32_t ksb = smb, vsb = smb + 25600;   // 400 rows x 64B each (SW64)

    const int tid = threadIdx.x, lane = tid & 31, warp = tid >> 5;
    const size_t hw = ((size_t)(w * NHEAD + head)) * NTOK * HEADD;
    const bf16* qb = qkv + hw;
    const bf16* kb = qkv + (size_t)MROWS * CC + hw;
    const bf16* vb = qkv + 2 * (size_t)MROWS * CC + hw;

    {
        int i = tid;
        int buf = (i >= 128);
        int j = i - buf * 128;
        *(uint32_t*)(sm + buf * 25600 + 392 * 64 + j * 4) = 0u;
    }
    for (int i = tid; i < NTOK * 4; i += 256) {
        int row = i >> 2, ch = i & 3;
        uint32_t s = swz64((uint32_t)(row * 64 + ch * 16));
        cp16(ksb + s, kb + row * 32 + ch * 8);
        cp16(vsb + s, vb + row * 32 + ch * 8);
    }
    asm volatile("cp.async.commit_group;\n");
    asm volatile("cp.async.wait_group 0;\n");
    __syncthreads();

    const int wtype = ((w >> 6) << 2) | ((((w >> 3) & 7) == 7) ? 2 : 0) | (((w & 7) == 7) ? 1 : 0);
    const float4* btb = btabF + ((size_t)(wtype * NHEAD + head) * 625) * 64 + lane;

    const int r  = lane >> 2, c2 = (lane & 3) * 2;
    const int lrow = (lane & 7) + ((lane & 16) ? 8 : 0);
    const int loff = (lane & 8) ? 16 : 0;
    const uint32_t s0 = swz64((uint32_t)(lrow * 64 + loff));

    for (int mt = warp; mt < 25; mt += 8) {
        const int m0r = mt * 16;
        uint32_t qa[2][4];
        #pragma unroll
        for (int kt = 0; kt < 2; ++kt) {
            qa[kt][0] = *(const uint32_t*)(qb + (m0r + r    ) * 32 + kt * 16 +     c2);
            qa[kt][1] = *(const uint32_t*)(qb + (m0r + r + 8) * 32 + kt * 16 +     c2);
            qa[kt][2] = *(const uint32_t*)(qb + (m0r + r    ) * 32 + kt * 16 + 8 + c2);
            qa[kt][3] = *(const uint32_t*)(qb + (m0r + r + 8) * 32 + kt * 16 + 8 + c2);
        }
        float oc[4][4];
        #pragma unroll
        for (int a = 0; a < 4; ++a)
            #pragma unroll
            for (int e = 0; e < 4; ++e) oc[a][e] = 0.f;
        float rs0 = 0.f, rs1 = 0.f;

        const float4* bt = btb + (size_t)(mt * 25) * 64;
        uint32_t ka0 = ksb + s0, ka1 = ksb + (s0 ^ 32u);
        uint32_t va0 = vsb + s0, va1 = vsb + (s0 ^ 32u);

        #pragma unroll 1
        for (int np = 0; np < 25; ++np) {
            float4 bA = bt[0];
            float4 bB = bt[32];
            uint32_t kf0[4], kf1[4];
            LDSM4(kf0, ka0);
            LDSM4(kf1, ka1);
            float sA[4] = {bA.x, bA.y, bA.z, bA.w};
            float sB[4] = {bB.x, bB.y, bB.z, bB.w};
            MMA16816(sA, qa[0][0], qa[0][1], qa[0][2], qa[0][3], kf0[0], kf0[1]);
            MMA16816(sA, qa[1][0], qa[1][1], qa[1][2], qa[1][3], kf1[0], kf1[1]);
            MMA16816(sB, qa[0][0], qa[0][1], qa[0][2], qa[0][3], kf0[2], kf0[3]);
            MMA16816(sB, qa[1][0], qa[1][1], qa[1][2], qa[1][3], kf1[2], kf1[3]);
            float e0 = ex2f(sA[0]), e1 = ex2f(sA[1]);
            float e2 = ex2f(sA[2]), e3 = ex2f(sA[3]);
            float e4 = ex2f(sB[0]), e5 = ex2f(sB[1]);
            float e6 = ex2f(sB[2]), e7 = ex2f(sB[3]);
            rs0 += (e0 + e1) + (e4 + e5);
            rs1 += (e2 + e3) + (e6 + e7);
            uint32_t pa0 = packbf(e0, e1), pa1 = packbf(e2, e3);
            uint32_t pa2 = packbf(e4, e5), pa3 = packbf(e6, e7);
            uint32_t vf0[4], vf1[4];
            LDSM4T(vf0, va0);
            LDSM4T(vf1, va1);
            MMA16816(oc[0], pa0, pa1, pa2, pa3, vf0[0], vf0[2]);
            MMA16816(oc[1], pa0, pa1, pa2, pa3, vf0[1], vf0[3]);
            MMA16816(oc[2], pa0, pa1, pa2, pa3, vf1[0], vf1[2]);
            MMA16816(oc[3], pa0, pa1, pa2, pa3, vf1[1], vf1[3]);
            ka0 += 1024; ka1 += 1024;
            va0 += 1024; va1 += 1024;
            bt  += 64;
        }
        rs0 += __shfl_xor_sync(~0u, rs0, 1); rs0 += __shfl_xor_sync(~0u, rs0, 2);
        rs1 += __shfl_xor_sync(~0u, rs1, 1); rs1 += __shfl_xor_sync(~0u, rs1, 2);
        float i0 = 1.f / rs0, i1 = 1.f / rs1;
        {
            size_t yb = ((size_t)(w * NTOK + m0r + r)) * CC + head * HEADD + c2;
            #pragma unroll
            for (int dt = 0; dt < 4; ++dt)
                *(uint32_t*)(y + yb + dt * 8) = packbf(oc[dt][0] * i0, oc[dt][1] * i0);
        }
        if (m0r + r + 8 < NTOK) {
            size_t yb = ((size_t)(w * NTOK + m0r + r + 8)) * CC + head * HEADD + c2;
            #pragma unroll
            for (int dt = 0; dt < 4; ++dt)
                *(uint32_t*)(y + yb + dt * 8) = packbf(oc[dt][2] * i1, oc[dt][3] * i1);
        }
    }
}

// ---------------- launch ----------------
extern "C" void kernel_launch(void* const* d_in, const int* in_sizes, int n_in,
                              void* d_out, int out_size) {
    (void)in_sizes; (void)n_in; (void)out_size;
    const float* x     = (const float*)d_in[0];
    const float* n1w   = (const float*)d_in[1];
    const float* n1b   = (const float*)d_in[2];
    const float* qkvw  = (const float*)d_in[3];
    const float* qkvb  = (const float*)d_in[4];
    const float* relt  = (const float*)d_in[5];
    const float* projw = (const float*)d_in[6];
    const float* projb = (const float*)d_in[7];
    const float* n2w   = (const float*)d_in[8];
    const float* n2b   = (const float*)d_in[9];
    const float* fc1w  = (const float*)d_in[10];
    const float* fc1b  = (const float*)d_in[11];
    const float* fc2w  = (const float*)d_in[12];
    const float* fc2b  = (const float*)d_in[13];

    bf16 *win, *qkvB, *yB, *m1, *hid, *wb;
    float *x1;
    float4 *btabF;
    cudaGetSymbolAddress((void**)&win,   g_win);
    cudaGetSymbolAddress((void**)&qkvB,  g_qkv);
    cudaGetSymbolAddress((void**)&yB,    g_y);
    cudaGetSymbolAddress((void**)&x1,    g_x1);
    cudaGetSymbolAddress((void**)&m1,    g_m1);
    cudaGetSymbolAddress((void**)&hid,   g_hid);
    cudaGetSymbolAddress((void**)&wb,    g_wb);
    cudaGetSymbolAddress((void**)&btabF, g_btabF);

    cudaFuncSetAttribute(attn_mma, cudaFuncAttributeMaxDynamicSharedMemorySize, SMEM_ATT);
    cudaFuncSetAttribute(attn_mma, cudaFuncAttributePreferredSharedMemoryCarveout, 100);
    cudaFuncSetAttribute(mgemm3<0,384,128>, cudaFuncAttributeMaxDynamicSharedMemorySize, SMEM_G2);
    cudaFuncSetAttribute(mgemm3<1,128,128>, cudaFuncAttributeMaxDynamicSharedMemorySize, SMEM_G2);
    cudaFuncSetAttribute(mgemm3<2,512,128>, cudaFuncAttributeMaxDynamicSharedMemorySize, SMEM_G2);
    cudaFuncSetAttribute(mgemm3<3,128,512>, cudaFuncAttributeMaxDynamicSharedMemorySize, SMEM_G2);

    prep_kernel<<<192 + 2500 + MROWS / 8, 256>>>(qkvw, projw, fc1w, fc2w, wb,
                                                 relt, btabF, x, n1w, n1b, win);
    mgemm3<0, 384, 128><<<dim3(392, 3), 256, SMEM_G2>>>(win, wb, qkvb,
        nullptr, nullptr, nullptr, nullptr, qkvB);
    attn_mma<<<NWIN * NHEAD, 256, SMEM_ATT>>>(qkvB, btabF, yB);
    mgemm3<1, 128, 128><<<dim3(392, 1), 256, SMEM_G2>>>(yB, wb + 49152, projb,
        x, n2w, n2b, m1, x1);
    mgemm3<2, 512, 128><<<dim3(392, 4), 256, SMEM_G2>>>(m1, wb + 65536, fc1b,
        nullptr, nullptr, nullptr, nullptr, hid);
    mgemm3<3, 128, 512><<<dim3(392, 1), 256, SMEM_G2>>>(hid, wb + 131072, fc2b,
        x1, nullptr, nullptr, nullptr, (float*)d_out);
}

// round 15
// speedup vs baseline: 1.0855x; 1.0154x over previous
#include <cuda_runtime.h>
#include <cuda_bf16.h>
#include <math.h>
#include <stdint.h>

// ---------------- problem constants ----------------
#define CC      128
#define NHEAD   4
#define HEADD   32
#define NTOK    392
#define NPAD    400
#define NWIN    128
#define MROWS   50176
#define HIDD    512
#define SCALE_Q 0.17677669529663687f
#define LOG2E   1.4426950408889634f
#define QSCALE  (0.25503489337494845f)   // SCALE_Q * LOG2E
#define SMEM_ATT  51200     // attention: Ks + Vs, 400 rows x 64B (SW64)
#define SMEM_G2   65536     // gemm: 2 stages x (A 16KB + B 16KB)

typedef __nv_bfloat16 bf16;

// ---------------- scratch (device globals) ----------------
__device__ __align__(16) bf16  g_win[MROWS * CC];
__device__ __align__(16) bf16  g_qkv[3 * MROWS * CC];   // bf16 (sel,w,head,n,d)
__device__ __align__(16) bf16  g_y[MROWS * CC];
__device__ __align__(16) float g_x1[MROWS * CC];
__device__ __align__(16) bf16  g_m1[MROWS * CC];
__device__ __align__(16) bf16  g_hid[MROWS * HIDD];
__device__ __align__(16) bf16  g_wb[196608];
__device__ __align__(16) float4 g_btabF[32 * 625 * 2 * 32]; // fp32 accumulator-frag bias*log2e

// ---------------- asm helpers ----------------
__device__ __forceinline__ void cp16(uint32_t dst, const void* src) {
    asm volatile("cp.async.cg.shared.global [%0], [%1], 16;\n" :: "r"(dst), "l"(src));
}
__device__ __forceinline__ uint32_t swz(int row, int kb) {        // SW128 (gemm)
    return (uint32_t)((row << 7) + (kb ^ ((row & 7) << 4)));
}
__device__ __forceinline__ uint32_t swz64(uint32_t off) {         // SW64 (attention)
    return off ^ ((off >> 3) & 0x30);
}
__device__ __forceinline__ float ex2f(float x) {
    float y;
    asm("ex2.approx.ftz.f32 %0, %1;" : "=f"(y) : "f"(x));
    return y;
}
#define LDSM4(R, addr) \
    asm volatile("ldmatrix.sync.aligned.m8n8.x4.shared.b16 {%0,%1,%2,%3}, [%4];\n" \
        : "=r"((R)[0]), "=r"((R)[1]), "=r"((R)[2]), "=r"((R)[3]) : "r"(addr))
#define LDSM4T(R, addr) \
    asm volatile("ldmatrix.sync.aligned.m8n8.x4.trans.shared.b16 {%0,%1,%2,%3}, [%4];\n" \
        : "=r"((R)[0]), "=r"((R)[1]), "=r"((R)[2]), "=r"((R)[3]) : "r"(addr))
#define MMA16816(d, a0,a1,a2,a3, b0,b1) \
    asm volatile("mma.sync.aligned.m16n8k16.row.col.f32.bf16.bf16.f32 " \
        "{%0,%1,%2,%3}, {%4,%5,%6,%7}, {%8,%9}, {%0,%1,%2,%3};\n" \
        : "+f"((d)[0]), "+f"((d)[1]), "+f"((d)[2]), "+f"((d)[3]) \
        : "r"(a0), "r"(a1), "r"(a2), "r"(a3), "r"(b0), "r"(b1))

__device__ __forceinline__ uint32_t packbf(float a, float b) {
    __nv_bfloat162 p = __floats2bfloat162_rn(a, b);
    return *(uint32_t*)&p;
}

// ---------------- prep + LN1 merged ----------------
__global__ void __launch_bounds__(256) prep_kernel(
        const float* __restrict__ s0, const float* __restrict__ s1,
        const float* __restrict__ s2, const float* __restrict__ s3,
        bf16* __restrict__ wb,
        const float* __restrict__ relt, float4* __restrict__ btabF,
        const float* __restrict__ x,
        const float* __restrict__ n1w, const float* __restrict__ n1b,
        bf16* __restrict__ win) {
    int b = blockIdx.x;
    if (b < 192) {                          // weight conversion: 49152 float4
        int i = b * 256 + threadIdx.x;
        const float* s; int off;
        if (i < 12288)      { s = s0; off = 0; }
        else if (i < 16384) { s = s1; off = 12288; }
        else if (i < 32768) { s = s2; off = 16384; }
        else                { s = s3; off = 32768; }
        float4 v = ((const float4*)s)[i - off];
        ((uint2*)wb)[i] = make_uint2(packbf(v.x, v.y), packbf(v.z, v.w));
        return;
    }
    if (b < 192 + 2500) {
        int gid = (b - 192) * 256 + threadIdx.x;
        int lane = gid & 31;
        int t    = gid >> 5;
        int tile = t % 625;
        int hw_  = t / 625;
        int head = hw_ & 3, wt = hw_ >> 2;
        int mt = tile / 25, np = tile % 25;
        int r = lane >> 2, cb = (lane & 3) * 2;
        float vv[2][4];
        #pragma unroll
        for (int ri = 0; ri < 2; ++ri) {
            int row = mt * 16 + r + ri * 8;
            bool rowpad = row >= NTOK;
            int tn = 0, hn = 0, wn_ = 0, regn = 0;
            if (!rowpad) {
                tn = row / 49; hn = (row / 7) % 7; wn_ = row % 7;
                regn = ((wt & 4) ? (tn  < 4 ? 1 : 2) : 0) * 9
                     + ((wt & 2) ? (hn  < 4 ? 1 : 2) : 0) * 3
                     + ((wt & 1) ? (wn_ < 4 ? 1 : 2) : 0);
            }
            #pragma unroll
            for (int ci = 0; ci < 4; ++ci) {
                int col = np * 16 + cb + (ci & 1) + (ci >> 1) * 8;
                float v;
                if (col >= NTOK)      v = -100.f * LOG2E;
                else if (rowpad)      v = 0.f;
                else {
                    int tm = col / 49, hm = (col / 7) % 7, wm_ = col % 7;
                    int regm = ((wt & 4) ? (tm  < 4 ? 1 : 2) : 0) * 9
                             + ((wt & 2) ? (hm  < 4 ? 1 : 2) : 0) * 3
                             + ((wt & 1) ? (wm_ < 4 ? 1 : 2) : 0);
                    int idx = (tn - tm + 7) * 169 + (hn - hm + 6) * 13 + (wn_ - wm_ + 6);
                    float bb = relt[idx * NHEAD + head];
                    v = ((regn == regm) ? bb : bb - 100.f) * LOG2E;
                }
                vv[ri][ci] = v;
            }
        }
        btabF[((size_t)t * 2 + 0) * 32 + lane] = make_float4(vv[0][0], vv[0][1], vv[1][0], vv[1][1]);
        btabF[((size_t)t * 2 + 1) * 32 + lane] = make_float4(vv[0][2], vv[0][3], vv[1][2], vv[1][3]);
        return;
    }
    // LN1 + cyclic shift + window partition (bf16 out)
    int row  = (b - 192 - 2500) * 8 + (threadIdx.x >> 5);
    int lane = threadIdx.x & 31;
    int w = row / NTOK, n = row % NTOK;
    int dblk = w >> 6, hblk = (w >> 3) & 7, wblk = w & 7;
    int t = n / 49, hh = (n / 7) % 7, ww = n % 7;
    int gd = (dblk * 8 + t + 4) & 15;
    int gh = hblk * 7 + hh + 3; if (gh >= 56) gh -= 56;
    int gx = wblk * 7 + ww + 3; if (gx >= 56) gx -= 56;
    int src = (gd * 56 + gh) * 56 + gx;
    float4 v = *(const float4*)(x + (size_t)src * CC + lane * 4);
    float s  = v.x + v.y + v.z + v.w;
    float ss = v.x*v.x + v.y*v.y + v.z*v.z + v.w*v.w;
    #pragma unroll
    for (int o = 16; o; o >>= 1) {
        s  += __shfl_xor_sync(~0u, s,  o);
        ss += __shfl_xor_sync(~0u, ss, o);
    }
    float mu  = s * (1.f / CC);
    float var = ss * (1.f / CC) - mu * mu;
    float rs  = rsqrtf(var + 1e-5f);
    float4 gwv = *(const float4*)(n1w + lane * 4);
    float4 gbv = *(const float4*)(n1b + lane * 4);
    *(uint2*)(win + (size_t)row * CC + lane * 4) = make_uint2(
        packbf((v.x - mu) * rs * gwv.x + gbv.x, (v.y - mu) * rs * gwv.y + gbv.y),
        packbf((v.z - mu) * rs * gwv.z + gbv.z, (v.w - mu) * rs * gwv.w + gbv.w));
}

// ---------------- GEMM v2: 128 thr, 4 warps @ 64x64, dbl-buffered frags (proj/fc2) ----------------
template<int EPI, int ND, int KK>
__global__ void __launch_bounds__(128) mgemm2(const bf16* __restrict__ A,
                                              const bf16* __restrict__ B,
                                              const float* __restrict__ bias,
                                              const float* __restrict__ extra,
                                              const float* __restrict__ lnw,
                                              const float* __restrict__ lnb,
                                              void* __restrict__ out2,
                                              void* __restrict__ outv) {
    extern __shared__ char smc[];
    const uint32_t smb = (uint32_t)__cvta_generic_to_shared(smc);
    const int tid = threadIdx.x, lane = tid & 31, warp = tid >> 5;
    const int wm = warp >> 1, wn = warp & 1;
    const int m0 = blockIdx.x * 128, n0 = blockIdx.y * 128;
    constexpr int NCHUNK = KK / 64;

    float c[4][8][4];
    #pragma unroll
    for (int a = 0; a < 4; ++a)
        #pragma unroll
        for (int b = 0; b < 8; ++b)
            #pragma unroll
            for (int e = 0; e < 4; ++e) c[a][b][e] = 0.f;

    auto load = [&](int ch, int st) {
        uint32_t ab = smb + st * 32768, bb = ab + 16384;
        const char* Ap = (const char*)(A + (size_t)m0 * KK + ch * 64);
        const char* Bp = (const char*)(B + (size_t)n0 * KK + ch * 64);
        #pragma unroll
        for (int i = 0; i < 8; ++i) {
            int cid = tid + i * 128;
            int row = cid >> 3, kb = (cid & 7) * 16;
            cp16(ab + swz(row, kb), Ap + (size_t)row * (KK * 2) + kb);
            cp16(bb + swz(row, kb), Bp + (size_t)row * (KK * 2) + kb);
        }
        asm volatile("cp.async.commit_group;\n");
    };

    load(0, 0);
    if (NCHUNK > 1) load(1, 1);
    asm volatile("cp.async.wait_group %0;\n" :: "n"(1));
    if (NCHUNK == 1) asm volatile("cp.async.wait_group 0;\n");
    __syncthreads();

    #pragma unroll 1
    for (int ch = 0; ch < NCHUNK; ++ch) {
        const int st = ch & 1;
        const uint32_t ab = smb + st * 32768, bb = ab + 16384;
        uint32_t af[2][4][4], bfr[2][4][4];
        auto ldf = [&](int ks, int u) {
            #pragma unroll
            for (int mi = 0; mi < 4; ++mi) {
                int row = wm * 64 + mi * 16 + (lane & 15);
                int kb  = ks * 32 + ((lane & 16) ? 16 : 0);
                LDSM4(af[u][mi], ab + swz(row, kb));
            }
            #pragma unroll
            for (int p = 0; p < 4; ++p) {
                int row = wn * 64 + p * 16 + (lane & 7) + ((lane & 16) ? 8 : 0);
                int kb  = ks * 32 + ((lane & 8) ? 16 : 0);
                LDSM4(bfr[u][p], bb + swz(row, kb));
            }
        };
        ldf(0, 0);
        #pragma unroll
        for (int ks = 0; ks < 4; ++ks) {
            if (ks < 3) ldf(ks + 1, (ks + 1) & 1);
            const int u = ks & 1;
            #pragma unroll
            for (int mi = 0; mi < 4; ++mi)
                #pragma unroll
                for (int p = 0; p < 4; ++p) {
                    MMA16816(c[mi][p*2],   af[u][mi][0], af[u][mi][1], af[u][mi][2], af[u][mi][3],
                             bfr[u][p][0], bfr[u][p][1]);
                    MMA16816(c[mi][p*2+1], af[u][mi][0], af[u][mi][1], af[u][mi][2], af[u][mi][3],
                             bfr[u][p][2], bfr[u][p][3]);
                }
        }
        __syncthreads();
        if (ch + 2 < NCHUNK) load(ch + 2, st);
        if (ch + 1 < NCHUNK) {
            if (ch + 2 < NCHUNK) asm volatile("cp.async.wait_group %0;\n" :: "n"(1));
            else                 asm volatile("cp.async.wait_group 0;\n");
            __syncthreads();
        }
    }

    const int colb = n0 + wn * 64 + (lane & 3) * 2;
    if (EPI == 1) {
        float* redS  = (float*)smc;                 // [2][128]
        float* redSS = redS + 256;
        __syncthreads();
        int lins[4][2];
        #pragma unroll
        for (int mi = 0; mi < 4; ++mi) {
            #pragma unroll
            for (int h = 0; h < 2; ++h) {
                int m = m0 + wm * 64 + mi * 16 + (lane >> 2) + h * 8;
                int w = m / NTOK, n = m % NTOK;
                int dblk = w >> 6, hblk = (w >> 3) & 7, wblk = w & 7;
                int t = n / 49, hh = (n / 7) % 7, ww = n % 7;
                int gd = (dblk * 8 + t + 4) & 15;
                int gh = hblk * 7 + hh + 3; if (gh >= 56) gh -= 56;
                int gx = wblk * 7 + ww + 3; if (gx >= 56) gx -= 56;
                int lin = ((gd * 56 + gh) * 56 + gx) * CC;
                lins[mi][h] = lin;
                float s = 0.f, ss = 0.f;
                #pragma unroll
                for (int ni = 0; ni < 8; ++ni) {
                    int j = colb + ni * 8;
                    float2 e = *(const float2*)(extra + lin + j);
                    float v0 = c[mi][ni][h*2+0] + bias[j]   + e.x;
                    float v1 = c[mi][ni][h*2+1] + bias[j+1] + e.y;
                    *(float2*)((float*)outv + lin + j) = make_float2(v0, v1);
                    c[mi][ni][h*2+0] = v0; c[mi][ni][h*2+1] = v1;
                    s  += v0 + v1;
                    ss += v0 * v0 + v1 * v1;
                }
                s  += __shfl_xor_sync(~0u, s, 1);  s  += __shfl_xor_sync(~0u, s, 2);
                ss += __shfl_xor_sync(~0u, ss, 1); ss += __shfl_xor_sync(~0u, ss, 2);
                if ((lane & 3) == 0) {
                    int rrow = wm * 64 + mi * 16 + (lane >> 2) + h * 8;
                    redS [wn * 128 + rrow] = s;
                    redSS[wn * 128 + rrow] = ss;
                }
            }
        }
        __syncthreads();
        bf16* o2 = (bf16*)out2;
        #pragma unroll
        for (int mi = 0; mi < 4; ++mi) {
            #pragma unroll
            for (int h = 0; h < 2; ++h) {
                int rrow = wm * 64 + mi * 16 + (lane >> 2) + h * 8;
                int lin = lins[mi][h];
                float S  = redS[rrow]  + redS[128 + rrow];
                float SS = redSS[rrow] + redSS[128 + rrow];
                float mu  = S * (1.f / CC);
                float var = SS * (1.f / CC) - mu * mu;
                float rs  = rsqrtf(var + 1e-5f);
                #pragma unroll
                for (int ni = 0; ni < 8; ++ni) {
                    int j = colb + ni * 8;
                    float2 gwv = *(const float2*)(lnw + j);
                    float2 gbv = *(const float2*)(lnb + j);
                    float v0 = (c[mi][ni][h*2+0] - mu) * rs * gwv.x + gbv.x;
                    float v1 = (c[mi][ni][h*2+1] - mu) * rs * gwv.y + gbv.y;
                    *(uint32_t*)(o2 + lin + j) = packbf(v0, v1);
                }
            }
        }
        return;
    }
    #pragma unroll
    for (int mi = 0; mi < 4; ++mi) {
        #pragma unroll
        for (int h = 0; h < 2; ++h) {
            int m = m0 + wm * 64 + mi * 16 + (lane >> 2) + h * 8;
            if (EPI == 3) {                 // FC2 + residual -> final fp32 out
                float* out = (float*)outv;
                #pragma unroll
                for (int ni = 0; ni < 8; ++ni) {
                    int j = colb + ni * 8;
                    float2 e = *(const float2*)(extra + (size_t)m * CC + j);
                    *(float2*)(out + (size_t)m * CC + j) = make_float2(
                        c[mi][ni][h*2+0] + bias[j]   + e.x,
                        c[mi][ni][h*2+1] + bias[j+1] + e.y);
                }
            }
        }
    }
}

// ---------------- GEMM v3: 256 thr, 8 warps @ 64x32 (qkv/fc1) ----------------
template<int EPI, int ND, int KK>
__global__ void __launch_bounds__(256) mgemm3(const bf16* __restrict__ A,
                                              const bf16* __restrict__ B,
                                              const float* __restrict__ bias,
                                              const float* __restrict__ extra,
                                              const float* __restrict__ lnw,
                                              const float* __restrict__ lnb,
                                              void* __restrict__ out2,
                                              void* __restrict__ outv) {
    extern __shared__ char smc[];
    const uint32_t smb = (uint32_t)__cvta_generic_to_shared(smc);
    const int tid = threadIdx.x, lane = tid & 31, warp = tid >> 5;
    const int wm = warp >> 2, wn = warp & 3;
    const int m0 = blockIdx.x * 128, n0 = blockIdx.y * 128;
    constexpr int NCHUNK = KK / 64;

    float c[4][4][4];
    #pragma unroll
    for (int a = 0; a < 4; ++a)
        #pragma unroll
        for (int b = 0; b < 4; ++b)
            #pragma unroll
            for (int e = 0; e < 4; ++e) c[a][b][e] = 0.f;

    auto load = [&](int ch, int st) {
        uint32_t ab = smb + st * 32768, bb = ab + 16384;
        const char* Ap = (const char*)(A + (size_t)m0 * KK + ch * 64);
        const char* Bp = (const char*)(B + (size_t)n0 * KK + ch * 64);
        #pragma unroll
        for (int i = 0; i < 4; ++i) {
            int cid = tid + i * 256;
            int row = cid >> 3, kb = (cid & 7) * 16;
            cp16(ab + swz(row, kb), Ap + (size_t)row * (KK * 2) + kb);
            cp16(bb + swz(row, kb), Bp + (size_t)row * (KK * 2) + kb);
        }
        asm volatile("cp.async.commit_group;\n");
    };

    load(0, 0);
    if (NCHUNK > 1) load(1, 1);
    asm volatile("cp.async.wait_group %0;\n" :: "n"(1));
    if (NCHUNK == 1) asm volatile("cp.async.wait_group 0;\n");
    __syncthreads();

    #pragma unroll 1
    for (int ch = 0; ch < NCHUNK; ++ch) {
        const int st = ch & 1;
        const uint32_t ab = smb + st * 32768, bb = ab + 16384;
        uint32_t af[2][4][4], bfr[2][2][4];
        auto ldf = [&](int ks, int u) {
            #pragma unroll
            for (int mi = 0; mi < 4; ++mi) {
                int row = wm * 64 + mi * 16 + (lane & 15);
                int kb  = ks * 32 + ((lane & 16) ? 16 : 0);
                LDSM4(af[u][mi], ab + swz(row, kb));
            }
            #pragma unroll
            for (int p = 0; p < 2; ++p) {
                int row = wn * 32 + p * 16 + (lane & 7) + ((lane & 16) ? 8 : 0);
                int kb  = ks * 32 + ((lane & 8) ? 16 : 0);
                LDSM4(bfr[u][p], bb + swz(row, kb));
            }
        };
        ldf(0, 0);
        #pragma unroll
        for (int ks = 0; ks < 4; ++ks) {
            if (ks < 3) ldf(ks + 1, (ks + 1) & 1);
            const int u = ks & 1;
            #pragma unroll
            for (int mi = 0; mi < 4; ++mi)
                #pragma unroll
                for (int p = 0; p < 2; ++p) {
                    MMA16816(c[mi][p*2],   af[u][mi][0], af[u][mi][1], af[u][mi][2], af[u][mi][3],
                             bfr[u][p][0], bfr[u][p][1]);
                    MMA16816(c[mi][p*2+1], af[u][mi][0], af[u][mi][1], af[u][mi][2], af[u][mi][3],
                             bfr[u][p][2], bfr[u][p][3]);
                }
        }
        __syncthreads();
        if (ch + 2 < NCHUNK) load(ch + 2, st);
        if (ch + 1 < NCHUNK) {
            if (ch + 2 < NCHUNK) asm volatile("cp.async.wait_group %0;\n" :: "n"(1));
            else                 asm volatile("cp.async.wait_group 0;\n");
            __syncthreads();
        }
    }

    const int colb = n0 + wn * 32 + (lane & 3) * 2;
    #pragma unroll
    for (int mi = 0; mi < 4; ++mi) {
        #pragma unroll
        for (int h = 0; h < 2; ++h) {
            int m = m0 + wm * 64 + mi * 16 + (lane >> 2) + h * 8;
            if (EPI == 0) {                 // QKV scatter (+scale q by QSCALE) -> bf16
                int w = m / NTOK, n = m % NTOK;
                bf16* out = (bf16*)outv;
                #pragma unroll
                for (int ni = 0; ni < 4; ++ni) {
                    int j = colb + ni * 8;
                    float v0 = c[mi][ni][h*2+0] + bias[j];
                    float v1 = c[mi][ni][h*2+1] + bias[j+1];
                    int sel = j >> 7, hd = (j >> 5) & 3, dch = j & 31;
                    if (sel == 0) { v0 *= QSCALE; v1 *= QSCALE; }
                    *(uint32_t*)(out + (size_t)(((sel*NWIN + w)*NHEAD + hd)*NTOK + n)*HEADD + dch)
                        = packbf(v0, v1);
                }
            } else {                        // FC1 + exact GELU -> bf16
                bf16* out = (bf16*)outv;
                #pragma unroll
                for (int ni = 0; ni < 4; ++ni) {
                    int j = colb + ni * 8;
                    float v0 = c[mi][ni][h*2+0] + bias[j];
                    float v1 = c[mi][ni][h*2+1] + bias[j+1];
                    v0 = 0.5f * v0 * (1.f + erff(v0 * 0.70710678118654752f));
                    v1 = 0.5f * v1 * (1.f + erff(v1 * 0.70710678118654752f));
                    *(uint32_t*)(out + (size_t)m * HIDD + j) = packbf(v0, v1);
                }
            }
        }
    }
}

// ---------------- bf16 HMMA attention: R13 (SW64, 4 CTAs/SM, bias-in-accumulator) ----------------
__global__ void __launch_bounds__(256, 4) attn_mma(const bf16* __restrict__ qkv,
                                                   const float4* __restrict__ btabF,
                                                   bf16* __restrict__ y) {
    const int w = blockIdx.x >> 2, head = blockIdx.x & 3;
    extern __shared__ char sm[];
    const uint32_t smb = (uint32_t)__cvta_generic_to_shared(sm);
    const uint32_t ksb = smb, vsb = smb + 25600;   // 400 rows x 64B each (SW64)

    const int tid = threadIdx.x, lane = tid & 31, warp = tid >> 5;
    const size_t hw = ((size_t)(w * NHEAD + head)) * NTOK * HEADD;
    const bf16* qb = qkv + hw;
    const bf16* kb = qkv + (size_t)MROWS * CC + hw;
    const bf16* vb = qkv + 2 * (size_t)MROWS * CC + hw;

    {
        int i = tid;
        int buf = (i >= 128);
        int j = i - buf * 128;
        *(uint32_t*)(sm + buf * 25600 + 392 * 64 + j * 4) = 0u;
    }
    for (int i = tid; i < NTOK * 4; i += 256) {
        int row = i >> 2, ch = i & 3;
        uint32_t s = swz64((uint32_t)(row * 64 + ch * 16));
        cp16(ksb + s, kb + row * 32 + ch * 8);
        cp16(vsb + s, vb + row * 32 + ch * 8);
    }
    asm volatile("cp.async.commit_group;\n");
    asm volatile("cp.async.wait_group 0;\n");
    __syncthreads();

    const int wtype = ((w >> 6) << 2) | ((((w >> 3) & 7) == 7) ? 2 : 0) | (((w & 7) == 7) ? 1 : 0);
    const float4* btb = btabF + ((size_t)(wtype * NHEAD + head) * 625) * 64 + lane;

    const int r  = lane >> 2, c2 = (lane & 3) * 2;
    const int lrow = (lane & 7) + ((lane & 16) ? 8 : 0);
    const int loff = (lane & 8) ? 16 : 0;
    const uint32_t s0 = swz64((uint32_t)(lrow * 64 + loff));

    for (int mt = warp; mt < 25; mt += 8) {
        const int m0r = mt * 16;
        uint32_t qa[2][4];
        #pragma unroll
        for (int kt = 0; kt < 2; ++kt) {
            qa[kt][0] = *(const uint32_t*)(qb + (m0r + r    ) * 32 + kt * 16 +     c2);
            qa[kt][1] = *(const uint32_t*)(qb + (m0r + r + 8) * 32 + kt * 16 +     c2);
            qa[kt][2] = *(const uint32_t*)(qb + (m0r + r    ) * 32 + kt * 16 + 8 + c2);
            qa[kt][3] = *(const uint32_t*)(qb + (m0r + r + 8) * 32 + kt * 16 + 8 + c2);
        }
        float oc[4][4];
        #pragma unroll
        for (int a = 0; a < 4; ++a)
            #pragma unroll
            for (int e = 0; e < 4; ++e) oc[a][e] = 0.f;
        float rs0 = 0.f, rs1 = 0.f;

        const float4* bt = btb + (size_t)(mt * 25) * 64;
        uint32_t ka0 = ksb + s0, ka1 = ksb + (s0 ^ 32u);
        uint32_t va0 = vsb + s0, va1 = vsb + (s0 ^ 32u);

        #pragma unroll 1
        for (int np = 0; np < 25; ++np) {
            float4 bA = bt[0];
            float4 bB = bt[32];
            uint32_t kf0[4], kf1[4];
            LDSM4(kf0, ka0);
            LDSM4(kf1, ka1);
            float sA[4] = {bA.x, bA.y, bA.z, bA.w};
            float sB[4] = {bB.x, bB.y, bB.z, bB.w};
            MMA16816(sA, qa[0][0], qa[0][1], qa[0][2], qa[0][3], kf0[0], kf0[1]);
            MMA16816(sA, qa[1][0], qa[1][1], qa[1][2], qa[1][3], kf1[0], kf1[1]);
            MMA16816(sB, qa[0][0], qa[0][1], qa[0][2], qa[0][3], kf0[2], kf0[3]);
            MMA16816(sB, qa[1][0], qa[1][1], qa[1][2], qa[1][3], kf1[2], kf1[3]);
            float e0 = ex2f(sA[0]), e1 = ex2f(sA[1]);
            float e2 = ex2f(sA[2]), e3 = ex2f(sA[3]);
            float e4 = ex2f(sB[0]), e5 = ex2f(sB[1]);
            float e6 = ex2f(sB[2]), e7 = ex2f(sB[3]);
            rs0 += (e0 + e1) + (e4 + e5);
            rs1 += (e2 + e3) + (e6 + e7);
            uint32_t pa0 = packbf(e0, e1), pa1 = packbf(e2, e3);
            uint32_t pa2 = packbf(e4, e5), pa3 = packbf(e6, e7);
            uint32_t vf0[4], vf1[4];
            LDSM4T(vf0, va0);
            LDSM4T(vf1, va1);
            MMA16816(oc[0], pa0, pa1, pa2, pa3, vf0[0], vf0[2]);
            MMA16816(oc[1], pa0, pa1, pa2, pa3, vf0[1], vf0[3]);
            MMA16816(oc[2], pa0, pa1, pa2, pa3, vf1[0], vf1[2]);
            MMA16816(oc[3], pa0, pa1, pa2, pa3, vf1[1], vf1[3]);
            ka0 += 1024; ka1 += 1024;
            va0 += 1024; va1 += 1024;
            bt  += 64;
        }
        rs0 += __shfl_xor_sync(~0u, rs0, 1); rs0 += __shfl_xor_sync(~0u, rs0, 2);
        rs1 += __shfl_xor_sync(~0u, rs1, 1); rs1 += __shfl_xor_sync(~0u, rs1, 2);
        float i0 = 1.f / rs0, i1 = 1.f / rs1;
        {
            size_t yb = ((size_t)(w * NTOK + m0r + r)) * CC + head * HEADD + c2;
            #pragma unroll
            for (int dt = 0; dt < 4; ++dt)
                *(uint32_t*)(y + yb + dt * 8) = packbf(oc[dt][0] * i0, oc[dt][1] * i0);
        }
        if (m0r + r + 8 < NTOK) {
            size_t yb = ((size_t)(w * NTOK + m0r + r + 8)) * CC + head * HEADD + c2;
            #pragma unroll
            for (int dt = 0; dt < 4; ++dt)
                *(uint32_t*)(y + yb + dt * 8) = packbf(oc[dt][2] * i1, oc[dt][3] * i1);
        }
    }
}

// ---------------- launch ----------------
extern "C" void kernel_launch(void* const* d_in, const int* in_sizes, int n_in,
                              void* d_out, int out_size) {
    (void)in_sizes; (void)n_in; (void)out_size;
    const float* x     = (const float*)d_in[0];
    const float* n1w   = (const float*)d_in[1];
    const float* n1b   = (const float*)d_in[2];
    const float* qkvw  = (const float*)d_in[3];
    const float* qkvb  = (const float*)d_in[4];
    const float* relt  = (const float*)d_in[5];
    const float* projw = (const float*)d_in[6];
    const float* projb = (const float*)d_in[7];
    const float* n2w   = (const float*)d_in[8];
    const float* n2b   = (const float*)d_in[9];
    const float* fc1w  = (const float*)d_in[10];
    const float* fc1b  = (const float*)d_in[11];
    const float* fc2w  = (const float*)d_in[12];
    const float* fc2b  = (const float*)d_in[13];

    bf16 *win, *qkvB, *yB, *m1, *hid, *wb;
    float *x1;
    float4 *btabF;
    cudaGetSymbolAddress((void**)&win,   g_win);
    cudaGetSymbolAddress((void**)&qkvB,  g_qkv);
    cudaGetSymbolAddress((void**)&yB,    g_y);
    cudaGetSymbolAddress((void**)&x1,    g_x1);
    cudaGetSymbolAddress((void**)&m1,    g_m1);
    cudaGetSymbolAddress((void**)&hid,   g_hid);
    cudaGetSymbolAddress((void**)&wb,    g_wb);
    cudaGetSymbolAddress((void**)&btabF, g_btabF);

    cudaFuncSetAttribute(attn_mma, cudaFuncAttributeMaxDynamicSharedMemorySize, SMEM_ATT);
    cudaFuncSetAttribute(attn_mma, cudaFuncAttributePreferredSharedMemoryCarveout, 100);
    cudaFuncSetAttribute(mgemm3<0,384,128>, cudaFuncAttributeMaxDynamicSharedMemorySize, SMEM_G2);
    cudaFuncSetAttribute(mgemm2<1,128,128>, cudaFuncAttributeMaxDynamicSharedMemorySize, SMEM_G2);
    cudaFuncSetAttribute(mgemm3<2,512,128>, cudaFuncAttributeMaxDynamicSharedMemorySize, SMEM_G2);
    cudaFuncSetAttribute(mgemm2<3,128,512>, cudaFuncAttributeMaxDynamicSharedMemorySize, SMEM_G2);

    prep_kernel<<<192 + 2500 + MROWS / 8, 256>>>(qkvw, projw, fc1w, fc2w, wb,
                                                 relt, btabF, x, n1w, n1b, win);
    mgemm3<0, 384, 128><<<dim3(392, 3), 256, SMEM_G2>>>(win, wb, qkvb,
        nullptr, nullptr, nullptr, nullptr, qkvB);
    attn_mma<<<NWIN * NHEAD, 256, SMEM_ATT>>>(qkvB, btabF, yB);
    mgemm2<1, 128, 128><<<dim3(392, 1), 128, SMEM_G2>>>(yB, wb + 49152, projb,
        x, n2w, n2b, m1, x1);
    mgemm3<2, 512, 128><<<dim3(392, 4), 256, SMEM_G2>>>(m1, wb + 65536, fc1b,
        nullptr, nullptr, nullptr, nullptr, hid);
    mgemm2<3, 128, 512><<<dim3(392, 1), 128, SMEM_G2>>>(hid, wb + 131072, fc2b,
        x1, nullptr, nullptr, nullptr, (float*)d_out);
}